// round 1
// baseline (speedup 1.0000x reference)
#include <cuda_runtime.h>
#include <cuda_bf16.h>

#define NN 4096
#define CC 128
#define LL 4
#define HEADS 4
#define HD 32
#define BN_EPS 1e-5f

// ---------------- scratch (static device globals; no allocation) ----------------
__device__ float g_x  [NN * CC];     // current layer input
__device__ float g_agg[NN * CC];     // gin aggregate / attn_o / m
__device__ float g_t1 [NN * 384];    // gin hidden / qkv / mlp hidden / t64
__device__ float g_t2 [NN * CC];     // g2 / o2 / h / t32
__device__ float g_h1 [NN * CC];
__device__ float g_h2 [NN * CC];

// ---------------- fast exp on FMA pipe (no MUFU) ----------------
__device__ __forceinline__ float fexp(float x) {
    x = fminf(fmaxf(x, -80.f), 60.f);
    float t  = x * 1.4426950408889634f;          // x * log2(e)
    float fi = t + 12582912.f;                   // 1.5 * 2^23 round trick
    int   i  = __float_as_int(fi) - 0x4B400000;
    float r  = t - (fi - 12582912.f);            // r in [-0.5, 0.5]
    float p  = 1.5401830e-4f;                    // Taylor of 2^r (deg 6)
    p = fmaf(p, r, 1.3333551e-3f);
    p = fmaf(p, r, 9.6181291e-3f);
    p = fmaf(p, r, 5.5504109e-2f);
    p = fmaf(p, r, 2.4022651e-1f);
    p = fmaf(p, r, 6.9314718e-1f);
    p = fmaf(p, r, 1.0f);
    return p * __int_as_float((i + 127) << 23);
}

// ---------------- elementwise helpers ----------------
__global__ void copy_kernel(const float* __restrict__ a, float* __restrict__ o, int n4) {
    int i = blockIdx.x * blockDim.x + threadIdx.x;
    if (i < n4) ((float4*)o)[i] = ((const float4*)a)[i];
}

__global__ void add_kernel(const float* __restrict__ a, const float* __restrict__ b,
                           float* __restrict__ o, int n4) {
    int i = blockIdx.x * blockDim.x + threadIdx.x;
    if (i < n4) {
        float4 x = ((const float4*)a)[i], y = ((const float4*)b)[i];
        ((float4*)o)[i] = make_float4(x.x + y.x, x.y + y.y, x.z + y.z, x.w + y.w);
    }
}

// ---------------- GIN scatter: agg[dst] += x[src]  (agg pre-initialized to x) --------
__global__ void scatter_kernel(const int* __restrict__ ei, const float* __restrict__ x,
                               float* __restrict__ agg, int E) {
    long id = (long)blockIdx.x * blockDim.x + threadIdx.x;
    if (id >= (long)E * CC) return;
    int e = (int)(id >> 7);
    int c = (int)(id & 127);
    int s = ei[e];
    int d = ei[E + e];
    atomicAdd(&agg[d * CC + c], x[s * CC + c]);
}

// ---------------- generic NT SGEMM: C[M,N] = act(A[M,K] @ B[N,K]^T + bias) ----------
template <bool RELU>
__global__ void gemm_nt(const float* __restrict__ A, const float* __restrict__ B,
                        const float* __restrict__ bias, float* __restrict__ C,
                        int M, int N, int K) {
    __shared__ float As[16][68];   // [k][m]
    __shared__ float Bs[16][68];   // [k][n]
    int tid = threadIdx.x;                 // 256
    int bm = blockIdx.y * 64, bn = blockIdx.x * 64;
    int ty = tid / 16, tx = tid % 16;
    int lr = tid / 4, lc = tid % 4;        // load: row 0..63, k-chunk 0..3
    float acc[4][4] = {};

    for (int k0 = 0; k0 < K; k0 += 16) {
        float4 av = make_float4(0.f, 0.f, 0.f, 0.f);
        int ar = bm + lr;
        if (ar < M) av = *(const float4*)&A[(long)ar * K + k0 + lc * 4];
        As[lc * 4 + 0][lr] = av.x; As[lc * 4 + 1][lr] = av.y;
        As[lc * 4 + 2][lr] = av.z; As[lc * 4 + 3][lr] = av.w;
        float4 bv = make_float4(0.f, 0.f, 0.f, 0.f);
        int br = bn + lr;
        if (br < N) bv = *(const float4*)&B[(long)br * K + k0 + lc * 4];
        Bs[lc * 4 + 0][lr] = bv.x; Bs[lc * 4 + 1][lr] = bv.y;
        Bs[lc * 4 + 2][lr] = bv.z; Bs[lc * 4 + 3][lr] = bv.w;
        __syncthreads();
#pragma unroll
        for (int kk = 0; kk < 16; kk++) {
            float4 a4 = *(const float4*)&As[kk][ty * 4];
            float4 b4 = *(const float4*)&Bs[kk][tx * 4];
            float a[4] = {a4.x, a4.y, a4.z, a4.w};
            float b[4] = {b4.x, b4.y, b4.z, b4.w};
#pragma unroll
            for (int i = 0; i < 4; i++)
#pragma unroll
                for (int j = 0; j < 4; j++) acc[i][j] = fmaf(a[i], b[j], acc[i][j]);
        }
        __syncthreads();
    }
#pragma unroll
    for (int i = 0; i < 4; i++) {
        int row = bm + ty * 4 + i;
        if (row >= M) continue;
#pragma unroll
        for (int j = 0; j < 4; j++) {
            int col = bn + tx * 4 + j;
            if (col >= N) continue;
            float v = acc[i][j] + bias[col];
            if (RELU) v = fmaxf(v, 0.f);
            C[(long)row * N + col] = v;
        }
    }
}

// ---------------- BatchNorm over rows: out = g*(in1+in2 - mean)*rsqrt(var+eps)+b ------
__global__ void bn_kernel(const float* __restrict__ in1, const float* __restrict__ in2,
                          const float* __restrict__ g, const float* __restrict__ b,
                          float* __restrict__ out) {
    int c = blockIdx.x;                    // one block per column, C=128 blocks
    __shared__ float col[NN];
    __shared__ float rs[256], rs2[256];
    int tid = threadIdx.x;                 // 256
    float s = 0.f, s2 = 0.f;
    for (int r = tid; r < NN; r += 256) {
        float v = in1[r * CC + c];
        if (in2) v += in2[r * CC + c];
        col[r] = v;
        s += v; s2 += v * v;
    }
    rs[tid] = s; rs2[tid] = s2;
    __syncthreads();
    for (int o = 128; o > 0; o >>= 1) {
        if (tid < o) { rs[tid] += rs[tid + o]; rs2[tid] += rs2[tid + o]; }
        __syncthreads();
    }
    float mean = rs[0] * (1.f / NN);
    float var  = rs2[0] * (1.f / NN) - mean * mean;
    float inv  = rsqrtf(var + BN_EPS) * g[c];
    float beta = b[c];
    for (int r = tid; r < NN; r += 256)
        out[r * CC + c] = (col[r] - mean) * inv + beta;
}

// ---------------- flash-style attention (no max pass; scores bounded) ----------------
// qkv: [NN][384] (q|k|v, head h at cols h*32). out: [NN][128].
#define BQ 64
#define BK 64
__global__ void flash_attn(const float* __restrict__ qkv, float* __restrict__ out) {
    __shared__ float Qs[BQ * 36];
    __shared__ float Ks[BK * 36];
    __shared__ float Vs[BK * 36];
    __shared__ float Ss[BQ * 68];
    __shared__ float ls[BQ];
    int tid = threadIdx.x;                 // 128
    int h = blockIdx.y;
    int qbase = blockIdx.x * BQ;
    int ty = tid >> 3, tx = tid & 7;
    int r0 = ty * 4, c0 = tx * 8;
    const float scale = 0.17677669529663687f;  // 1/sqrt(32)

    // load Q tile
#pragma unroll
    for (int t = 0; t < 4; t++) {
        int id = tid + t * 128;
        int row = id >> 3, c4 = id & 7;
        *(float4*)&Qs[row * 36 + c4 * 4] =
            *(const float4*)&qkv[(long)(qbase + row) * 384 + h * 32 + c4 * 4];
    }
    if (tid < BQ) ls[tid] = 0.f;
    float acc[4][4] = {};

    for (int kt = 0; kt < NN / BK; kt++) {
        __syncthreads();   // prior stage-O reads of Ss/Vs done before refill
        int kb = kt * BK;
#pragma unroll
        for (int t = 0; t < 4; t++) {
            int id = tid + t * 128;
            int row = id >> 3, c4 = id & 7;
            *(float4*)&Ks[row * 36 + c4 * 4] =
                *(const float4*)&qkv[(long)(kb + row) * 384 + 128 + h * 32 + c4 * 4];
            *(float4*)&Vs[row * 36 + c4 * 4] =
                *(const float4*)&qkv[(long)(kb + row) * 384 + 256 + h * 32 + c4 * 4];
        }
        __syncthreads();

        // scores: thread owns 4 q-rows x 8 k-cols
        float s[4][8] = {};
#pragma unroll
        for (int d4 = 0; d4 < 8; d4++) {
            float4 qv[4], kv[8];
#pragma unroll
            for (int i = 0; i < 4; i++) qv[i] = *(const float4*)&Qs[(r0 + i) * 36 + d4 * 4];
#pragma unroll
            for (int j = 0; j < 8; j++) kv[j] = *(const float4*)&Ks[(c0 + j) * 36 + d4 * 4];
#pragma unroll
            for (int i = 0; i < 4; i++)
#pragma unroll
                for (int j = 0; j < 8; j++) {
                    s[i][j] = fmaf(qv[i].x, kv[j].x, s[i][j]);
                    s[i][j] = fmaf(qv[i].y, kv[j].y, s[i][j]);
                    s[i][j] = fmaf(qv[i].z, kv[j].z, s[i][j]);
                    s[i][j] = fmaf(qv[i].w, kv[j].w, s[i][j]);
                }
        }
        // exp + row-sum + stage P to smem
#pragma unroll
        for (int i = 0; i < 4; i++) {
            float lp = 0.f;
#pragma unroll
            for (int j = 0; j < 8; j++) {
                float p = fexp(s[i][j] * scale);
                s[i][j] = p;
                lp += p;
            }
            atomicAdd(&ls[r0 + i], lp);
            *(float4*)&Ss[(r0 + i) * 68 + c0]     = make_float4(s[i][0], s[i][1], s[i][2], s[i][3]);
            *(float4*)&Ss[(r0 + i) * 68 + c0 + 4] = make_float4(s[i][4], s[i][5], s[i][6], s[i][7]);
        }
        __syncthreads();

        // O += P @ V : thread owns same 4 q-rows x 4 d-cols (tx*4)
#pragma unroll
        for (int j4 = 0; j4 < 16; j4++) {
            float4 p4[4], v4[4];
#pragma unroll
            for (int i = 0; i < 4; i++) p4[i] = *(const float4*)&Ss[(r0 + i) * 68 + j4 * 4];
#pragma unroll
            for (int jj = 0; jj < 4; jj++) v4[jj] = *(const float4*)&Vs[(j4 * 4 + jj) * 36 + tx * 4];
#pragma unroll
            for (int i = 0; i < 4; i++) {
                const float* pp = (const float*)&p4[i];
#pragma unroll
                for (int jj = 0; jj < 4; jj++) {
                    float pv = pp[jj];
                    acc[i][0] = fmaf(pv, v4[jj].x, acc[i][0]);
                    acc[i][1] = fmaf(pv, v4[jj].y, acc[i][1]);
                    acc[i][2] = fmaf(pv, v4[jj].z, acc[i][2]);
                    acc[i][3] = fmaf(pv, v4[jj].w, acc[i][3]);
                }
            }
        }
    }
    __syncthreads();
#pragma unroll
    for (int i = 0; i < 4; i++) {
        float inv = 1.f / ls[r0 + i];
        float4 o = make_float4(acc[i][0] * inv, acc[i][1] * inv, acc[i][2] * inv, acc[i][3] * inv);
        *(float4*)&out[(long)(qbase + r0 + i) * CC + h * 32 + tx * 4] = o;
    }
}

// ---------------- final head dot: out[n] = t32[n] . w + b ----------------
__global__ void head_final(const float* __restrict__ t32, const float* __restrict__ w,
                           const float* __restrict__ b, float* __restrict__ out) {
    int n = blockIdx.x * blockDim.x + threadIdx.x;
    if (n >= NN) return;
    float s = b[0];
#pragma unroll
    for (int k = 0; k < 32; k++) s = fmaf(t32[n * 32 + k], w[k], s);
    out[n] = s;
}

// ---------------- host orchestration ----------------
static void launch_gemm(const float* A, const float* B, const float* bias, float* C,
                        int M, int N, int K, bool relu) {
    dim3 grid((N + 63) / 64, (M + 63) / 64);
    if (relu) gemm_nt<true><<<grid, 256>>>(A, B, bias, C, M, N, K);
    else      gemm_nt<false><<<grid, 256>>>(A, B, bias, C, M, N, K);
}

extern "C" void kernel_launch(void* const* d_in, const int* in_sizes, int n_in,
                              void* d_out, int out_size) {
    const float* x_in      = (const float*)d_in[0];
    const int*   edge      = (const int*)  d_in[1];
    const float* gin_w1    = (const float*)d_in[2];
    const float* gin_b1    = (const float*)d_in[3];
    const float* gin_w2    = (const float*)d_in[4];
    const float* gin_b2    = (const float*)d_in[5];
    const float* attn_in_w = (const float*)d_in[6];
    const float* attn_in_b = (const float*)d_in[7];
    const float* attn_o_w  = (const float*)d_in[8];
    const float* attn_o_b  = (const float*)d_in[9];
    const float* n1_g = (const float*)d_in[10];
    const float* n1_b = (const float*)d_in[11];
    const float* n2_g = (const float*)d_in[12];
    const float* n2_b = (const float*)d_in[13];
    const float* n3_g = (const float*)d_in[14];
    const float* n3_b = (const float*)d_in[15];
    const float* mlp_w1 = (const float*)d_in[16];
    const float* mlp_b1 = (const float*)d_in[17];
    const float* mlp_w2 = (const float*)d_in[18];
    const float* mlp_b2 = (const float*)d_in[19];
    const float* hw1 = (const float*)d_in[20];
    const float* hb1 = (const float*)d_in[21];
    const float* hw2 = (const float*)d_in[22];
    const float* hb2 = (const float*)d_in[23];
    const float* hw3 = (const float*)d_in[24];
    const float* hb3 = (const float*)d_in[25];
    float* out = (float*)d_out;

    int E = in_sizes[1] / 2;

    float *p_x, *p_agg, *p_t1, *p_t2, *p_h1, *p_h2;
    cudaGetSymbolAddress((void**)&p_x,  g_x);
    cudaGetSymbolAddress((void**)&p_agg, g_agg);
    cudaGetSymbolAddress((void**)&p_t1, g_t1);
    cudaGetSymbolAddress((void**)&p_t2, g_t2);
    cudaGetSymbolAddress((void**)&p_h1, g_h1);
    cudaGetSymbolAddress((void**)&p_h2, g_h2);

    const int NC4 = NN * CC / 4;  // float4 count for a [NN,CC] tensor

    // x = input
    copy_kernel<<<(NC4 + 255) / 256, 256>>>(x_in, p_x, NC4);

    for (int i = 0; i < LL; i++) {
        const float* gw1 = gin_w1 + (long)i * CC * CC;
        const float* gb1 = gin_b1 + (long)i * CC;
        const float* gw2 = gin_w2 + (long)i * CC * CC;
        const float* gb2 = gin_b2 + (long)i * CC;
        const float* aiw = attn_in_w + (long)i * 3 * CC * CC;
        const float* aib = attn_in_b + (long)i * 3 * CC;
        const float* aow = attn_o_w + (long)i * CC * CC;
        const float* aob = attn_o_b + (long)i * CC;
        const float* mw1 = mlp_w1 + (long)i * 2 * CC * CC;
        const float* mb1 = mlp_b1 + (long)i * 2 * CC;
        const float* mw2 = mlp_w2 + (long)i * CC * 2 * CC;
        const float* mb2 = mlp_b2 + (long)i * CC;

        // ---- GIN branch ----
        copy_kernel<<<(NC4 + 255) / 256, 256>>>(p_x, p_agg, NC4);   // agg = x (eps=0 self term)
        long nsc = (long)E * CC;
        scatter_kernel<<<(int)((nsc + 255) / 256), 256>>>(edge, p_x, p_agg, E);
        launch_gemm(p_agg, gw1, gb1, p_t1, NN, CC, CC, true);       // relu(.)
        launch_gemm(p_t1, gw2, gb2, p_t2, NN, CC, CC, false);
        bn_kernel<<<CC, 256>>>(p_t2, p_x, n1_g + i * CC, n1_b + i * CC, p_h1);

        // ---- attention branch ----
        launch_gemm(p_x, aiw, aib, p_t1, NN, 3 * CC, CC, false);    // qkv
        flash_attn<<<dim3(NN / BQ, HEADS), 128>>>(p_t1, p_agg);     // attn_o -> agg
        launch_gemm(p_agg, aow, aob, p_t2, NN, CC, CC, false);      // out proj
        bn_kernel<<<CC, 256>>>(p_t2, p_x, n2_g + i * CC, n2_b + i * CC, p_h2);

        // ---- merge + MLP ----
        add_kernel<<<(NC4 + 255) / 256, 256>>>(p_h1, p_h2, p_t2, NC4);   // h
        launch_gemm(p_t2, mw1, mb1, p_t1, NN, 2 * CC, CC, true);
        launch_gemm(p_t1, mw2, mb2, p_agg, NN, CC, 2 * CC, false);       // m
        bn_kernel<<<CC, 256>>>(p_t2, p_agg, n3_g + i * CC, n3_b + i * CC, p_x);  // x = BN(h+m)
    }

    // ---- head MLP ----
    launch_gemm(p_x, hw1, hb1, p_t1, NN, CC / 2, CC, true);      // 4096x64
    launch_gemm(p_t1, hw2, hb2, p_t2, NN, CC / 4, CC / 2, true); // 4096x32
    head_final<<<(NN + 255) / 256, 256>>>(p_t2, hw3, hb3, out);
}

// round 3
// speedup vs baseline: 4.8315x; 4.8315x over previous
#include <cuda_runtime.h>
#include <cuda_bf16.h>
#include <cstdint>

#define NN 4096
#define CC 128
#define LL 4
#define HEADS 4
#define BN_EPS 1e-5f

// ---------------- scratch (static device globals; no allocation) ----------------
__device__ float g_x  [NN * CC];
__device__ float g_agg[NN * CC];
__device__ float g_t1 [NN * 384];
__device__ float g_t2 [NN * CC];
__device__ float g_h1 [NN * CC];
__device__ float g_h2 [NN * CC];
__device__ __nv_bfloat16 g_qb [HEADS * NN * 32];
__device__ __nv_bfloat16 g_kb [HEADS * NN * 32];
__device__ __nv_bfloat16 g_vtb[HEADS * 32 * NN];

// ---------------- mma.sync helpers (sm_80+ ISA, runs on sm_100 fallback HMMA) -----
__device__ __forceinline__ void mma_bf16(float* d, uint32_t a0, uint32_t a1, uint32_t a2,
                                         uint32_t a3, uint32_t b0, uint32_t b1) {
    asm volatile(
        "mma.sync.aligned.m16n8k16.row.col.f32.bf16.bf16.f32 "
        "{%0,%1,%2,%3}, {%4,%5,%6,%7}, {%8,%9}, {%0,%1,%2,%3};"
        : "+f"(d[0]), "+f"(d[1]), "+f"(d[2]), "+f"(d[3])
        : "r"(a0), "r"(a1), "r"(a2), "r"(a3), "r"(b0), "r"(b1));
}
__device__ __forceinline__ float fast_exp2(float x) {
    float y; asm("ex2.approx.ftz.f32 %0, %1;" : "=f"(y) : "f"(x)); return y;
}
__device__ __forceinline__ uint32_t pack_bf16(float lo, float hi) {
    uint32_t r; asm("cvt.rn.bf16x2.f32 %0, %1, %2;" : "=r"(r) : "f"(hi), "f"(lo)); return r;
}

// ---------------- elementwise helpers ----------------
__global__ void copy_kernel(const float* __restrict__ a, float* __restrict__ o, int n4) {
    int i = blockIdx.x * blockDim.x + threadIdx.x;
    if (i < n4) ((float4*)o)[i] = ((const float4*)a)[i];
}
__global__ void add_kernel(const float* __restrict__ a, const float* __restrict__ b,
                           float* __restrict__ o, int n4) {
    int i = blockIdx.x * blockDim.x + threadIdx.x;
    if (i < n4) {
        float4 x = ((const float4*)a)[i], y = ((const float4*)b)[i];
        ((float4*)o)[i] = make_float4(x.x + y.x, x.y + y.y, x.z + y.z, x.w + y.w);
    }
}

// ---------------- GIN scatter ----------------
__global__ void scatter_kernel(const int* __restrict__ ei, const float* __restrict__ x,
                               float* __restrict__ agg, int E) {
    long id = (long)blockIdx.x * blockDim.x + threadIdx.x;
    if (id >= (long)E * CC) return;
    int e = (int)(id >> 7);
    int c = (int)(id & 127);
    int s = ei[e];
    int d = ei[E + e];
    atomicAdd(&agg[d * CC + c], x[s * CC + c]);
}

// ---------------- NT SGEMM 64x32 tile, 128 threads ----------------
// C[M,N] = act(A[M,K] @ B[N,K]^T + bias). M%64==0, N%32==0, K%16==0.
template <bool RELU>
__global__ __launch_bounds__(128) void gemm_nt(const float* __restrict__ A,
                        const float* __restrict__ B, const float* __restrict__ bias,
                        float* __restrict__ C, int M, int N, int K) {
    __shared__ float As[16][68];
    __shared__ float Bs[16][36];
    int tid = threadIdx.x;
    int bm = blockIdx.y * 64, bn = blockIdx.x * 32;
    int ty = tid >> 3, tx = tid & 7;       // 16 x 8
    int lr = tid >> 2, lc = tid & 3;       // 32 x 4
    float acc[4][4] = {};
    for (int k0 = 0; k0 < K; k0 += 16) {
#pragma unroll
        for (int it = 0; it < 2; it++) {
            int r = lr + it * 32;
            float4 av = *(const float4*)&A[(long)(bm + r) * K + k0 + lc * 4];
            As[lc * 4 + 0][r] = av.x; As[lc * 4 + 1][r] = av.y;
            As[lc * 4 + 2][r] = av.z; As[lc * 4 + 3][r] = av.w;
        }
        {
            float4 bv = *(const float4*)&B[(long)(bn + lr) * K + k0 + lc * 4];
            Bs[lc * 4 + 0][lr] = bv.x; Bs[lc * 4 + 1][lr] = bv.y;
            Bs[lc * 4 + 2][lr] = bv.z; Bs[lc * 4 + 3][lr] = bv.w;
        }
        __syncthreads();
#pragma unroll
        for (int kk = 0; kk < 16; kk++) {
            float4 a4 = *(const float4*)&As[kk][ty * 4];
            float4 b4 = *(const float4*)&Bs[kk][tx * 4];
            float a[4] = {a4.x, a4.y, a4.z, a4.w};
            float b[4] = {b4.x, b4.y, b4.z, b4.w};
#pragma unroll
            for (int i = 0; i < 4; i++)
#pragma unroll
                for (int j = 0; j < 4; j++) acc[i][j] = fmaf(a[i], b[j], acc[i][j]);
        }
        __syncthreads();
    }
    float4 bb = *(const float4*)&bias[bn + tx * 4];
#pragma unroll
    for (int i = 0; i < 4; i++) {
        int row = bm + ty * 4 + i;
        float4 o = make_float4(acc[i][0] + bb.x, acc[i][1] + bb.y,
                               acc[i][2] + bb.z, acc[i][3] + bb.w);
        if (RELU) {
            o.x = fmaxf(o.x, 0.f); o.y = fmaxf(o.y, 0.f);
            o.z = fmaxf(o.z, 0.f); o.w = fmaxf(o.w, 0.f);
        }
        *(float4*)&C[(long)row * N + bn + tx * 4] = o;
    }
}

// ---------------- BatchNorm ----------------
__global__ void bn_kernel(const float* __restrict__ in1, const float* __restrict__ in2,
                          const float* __restrict__ g, const float* __restrict__ b,
                          float* __restrict__ out) {
    int c = blockIdx.x;
    __shared__ float col[NN];
    __shared__ float rs[256], rs2[256];
    int tid = threadIdx.x;
    float s = 0.f, s2 = 0.f;
    for (int r = tid; r < NN; r += 256) {
        float v = in1[r * CC + c];
        if (in2) v += in2[r * CC + c];
        col[r] = v;
        s += v; s2 += v * v;
    }
    rs[tid] = s; rs2[tid] = s2;
    __syncthreads();
    for (int o = 128; o > 0; o >>= 1) {
        if (tid < o) { rs[tid] += rs[tid + o]; rs2[tid] += rs2[tid + o]; }
        __syncthreads();
    }
    float mean = rs[0] * (1.f / NN);
    float var  = rs2[0] * (1.f / NN) - mean * mean;
    float inv  = rsqrtf(var + BN_EPS) * g[c];
    float beta = b[c];
    for (int r = tid; r < NN; r += 256)
        out[r * CC + c] = (col[r] - mean) * inv + beta;
}

// ---------------- qkv fp32 -> bf16 Q/K/V^T ----------------
__global__ void qkv_convert(const float* __restrict__ qkv, __nv_bfloat16* __restrict__ qb,
                            __nv_bfloat16* __restrict__ kb, __nv_bfloat16* __restrict__ vtb) {
    int id = blockIdx.x * 256 + threadIdx.x;
    int n = id >> 7, c = id & 127;
    int h = c >> 5, d = c & 31;
    float q = qkv[n * 384 + c];
    float k = qkv[n * 384 + 128 + c];
    float v = qkv[n * 384 + 256 + c];
    qb [((h << 12) + n) * 32 + d] = __float2bfloat16(q);
    kb [((h << 12) + n) * 32 + d] = __float2bfloat16(k);
    vtb[((h * 32 + d) << 12) + n] = __float2bfloat16(v);
}

// ---------------- mma.sync flash attention ----------------
// Block: (128-row q-tile, head). 8 warps x 32 lanes. Warp w owns q-rows [w*16, w*16+16).
// exp2 scale: log2(e)/sqrt(32)
#define EXP2_SCALE 0.25503480f
#define QK_STRIDE 40     // bf16 units per row (padded; conflict-free quad loads)
#define VT_STRIDE 136

__global__ __launch_bounds__(256, 1) void mma_attn(const __nv_bfloat16* __restrict__ qb,
        const __nv_bfloat16* __restrict__ kb, const __nv_bfloat16* __restrict__ vtb,
        float* __restrict__ out) {
    __shared__ uint16_t Qs[128 * QK_STRIDE];
    __shared__ uint16_t Ks[128 * QK_STRIDE];
    __shared__ uint16_t Vts[32 * VT_STRIDE];

    const int tid = threadIdx.x;
    const int wid = tid >> 5, lane = tid & 31;
    const int gid = lane >> 2, tig = lane & 3;     // group-of-4 row, in-group col
    const int h = blockIdx.y;
    const int qbase = blockIdx.x * 128;
    const int r0 = wid * 16;

    // ---- load Q tile: 128 rows x 32 bf16 ----
    const uint16_t* Qg = (const uint16_t*)(qb + ((long)h * NN + qbase) * 32);
#pragma unroll
    for (int it = 0; it < 2; it++) {
        int i = tid + it * 256;                 // 0..511 : row = i>>2, seg = i&3 (8 bf16)
        int row = i >> 2, seg = i & 3;
        *(uint4*)&Qs[row * QK_STRIDE + seg * 8] = *(const uint4*)&Qg[row * 32 + seg * 8];
    }
    __syncthreads();

    // preload Q fragments (2 k-steps of 16)
    uint32_t aq[2][4];
#pragma unroll
    for (int t = 0; t < 2; t++) {
        int k = t * 16 + tig * 2;
        aq[t][0] = *(const uint32_t*)&Qs[(r0 + gid    ) * QK_STRIDE + k    ];
        aq[t][1] = *(const uint32_t*)&Qs[(r0 + gid + 8) * QK_STRIDE + k    ];
        aq[t][2] = *(const uint32_t*)&Qs[(r0 + gid    ) * QK_STRIDE + k + 8];
        aq[t][3] = *(const uint32_t*)&Qs[(r0 + gid + 8) * QK_STRIDE + k + 8];
    }

    float oacc[4][4] = {};
    float rs0 = 0.f, rs1 = 0.f;   // partial row sums (rows r0+gid, r0+gid+8)

    for (int kt = 0; kt < NN / 128; kt++) {
        const int kb0 = kt * 128;
        __syncthreads();   // previous iteration's mma reads done
        // ---- load K tile (128 x 32) ----
        const uint16_t* Kg = (const uint16_t*)(kb + ((long)h * NN + kb0) * 32);
#pragma unroll
        for (int it = 0; it < 2; it++) {
            int i = tid + it * 256;
            int row = i >> 2, seg = i & 3;
            *(uint4*)&Ks[row * QK_STRIDE + seg * 8] = *(const uint4*)&Kg[row * 32 + seg * 8];
        }
        // ---- load V^T tile (32 x 128) ----
        const uint16_t* Vg = (const uint16_t*)(vtb + ((long)h * 32) * NN + kb0);
#pragma unroll
        for (int it = 0; it < 2; it++) {
            int i = tid + it * 256;
            int d = i >> 4, seg = i & 15;       // 32 rows x 16 segs of 8
            *(uint4*)&Vts[d * VT_STRIDE + seg * 8] = *(const uint4*)&Vg[(long)d * NN + seg * 8];
        }
        __syncthreads();

        // ---- S = Q @ K^T : 16 n-blocks of 8 cols ----
        float sacc[16][4];
#pragma unroll
        for (int j = 0; j < 16; j++) { sacc[j][0] = sacc[j][1] = sacc[j][2] = sacc[j][3] = 0.f; }
#pragma unroll
        for (int j = 0; j < 16; j++) {
#pragma unroll
            for (int t = 0; t < 2; t++) {
                int k = t * 16 + tig * 2;
                uint32_t b0 = *(const uint32_t*)&Ks[(8 * j + gid) * QK_STRIDE + k    ];
                uint32_t b1 = *(const uint32_t*)&Ks[(8 * j + gid) * QK_STRIDE + k + 8];
                mma_bf16(sacc[j], aq[t][0], aq[t][1], aq[t][2], aq[t][3], b0, b1);
            }
        }

        // ---- softmax (no-max; scores bounded) -> P fragments in registers ----
        uint32_t pf[16][2];
#pragma unroll
        for (int j = 0; j < 16; j++) {
            float p0 = fast_exp2(sacc[j][0] * EXP2_SCALE);
            float p1 = fast_exp2(sacc[j][1] * EXP2_SCALE);
            float p2 = fast_exp2(sacc[j][2] * EXP2_SCALE);
            float p3 = fast_exp2(sacc[j][3] * EXP2_SCALE);
            rs0 += p0 + p1;
            rs1 += p2 + p3;
            pf[j][0] = pack_bf16(p0, p1);
            pf[j][1] = pack_bf16(p2, p3);
        }

        // ---- O += P @ V^T : 4 d-blocks x 8 k-chunks ----
#pragma unroll
        for (int t = 0; t < 8; t++) {
            uint32_t a0 = pf[2 * t][0], a1 = pf[2 * t][1];
            uint32_t a2 = pf[2 * t + 1][0], a3 = pf[2 * t + 1][1];
            int k = t * 16 + tig * 2;
#pragma unroll
            for (int n = 0; n < 4; n++) {
                uint32_t b0 = *(const uint32_t*)&Vts[(8 * n + gid) * VT_STRIDE + k    ];
                uint32_t b1 = *(const uint32_t*)&Vts[(8 * n + gid) * VT_STRIDE + k + 8];
                mma_bf16(oacc[n], a0, a1, a2, a3, b0, b1);
            }
        }
    }

    // ---- reduce row sums across the quad ----
    rs0 += __shfl_xor_sync(0xFFFFFFFF, rs0, 1);
    rs0 += __shfl_xor_sync(0xFFFFFFFF, rs0, 2);
    rs1 += __shfl_xor_sync(0xFFFFFFFF, rs1, 1);
    rs1 += __shfl_xor_sync(0xFFFFFFFF, rs1, 2);
    float inv0 = 1.f / rs0, inv1 = 1.f / rs1;

    // ---- write O ----
    int rowA = qbase + r0 + gid, rowB = rowA + 8;
    float* poA = out + (long)rowA * CC + h * 32 + tig * 2;
    float* poB = out + (long)rowB * CC + h * 32 + tig * 2;
#pragma unroll
    for (int n = 0; n < 4; n++) {
        *(float2*)(poA + n * 8) = make_float2(oacc[n][0] * inv0, oacc[n][1] * inv0);
        *(float2*)(poB + n * 8) = make_float2(oacc[n][2] * inv1, oacc[n][3] * inv1);
    }
}

// ---------------- final head dot ----------------
__global__ void head_final(const float* __restrict__ t32, const float* __restrict__ w,
                           const float* __restrict__ b, float* __restrict__ out) {
    int n = blockIdx.x * blockDim.x + threadIdx.x;
    if (n >= NN) return;
    float s = b[0];
#pragma unroll
    for (int k = 0; k < 32; k++) s = fmaf(t32[n * 32 + k], w[k], s);
    out[n] = s;
}

// ---------------- host orchestration ----------------
static void launch_gemm(const float* A, const float* B, const float* bias, float* C,
                        int M, int N, int K, bool relu) {
    dim3 grid(N / 32, M / 64);
    if (relu) gemm_nt<true><<<grid, 128>>>(A, B, bias, C, M, N, K);
    else      gemm_nt<false><<<grid, 128>>>(A, B, bias, C, M, N, K);
}

extern "C" void kernel_launch(void* const* d_in, const int* in_sizes, int n_in,
                              void* d_out, int out_size) {
    const float* x_in      = (const float*)d_in[0];
    const int*   edge      = (const int*)  d_in[1];
    const float* gin_w1    = (const float*)d_in[2];
    const float* gin_b1    = (const float*)d_in[3];
    const float* gin_w2    = (const float*)d_in[4];
    const float* gin_b2    = (const float*)d_in[5];
    const float* attn_in_w = (const float*)d_in[6];
    const float* attn_in_b = (const float*)d_in[7];
    const float* attn_o_w  = (const float*)d_in[8];
    const float* attn_o_b  = (const float*)d_in[9];
    const float* n1_g = (const float*)d_in[10];
    const float* n1_b = (const float*)d_in[11];
    const float* n2_g = (const float*)d_in[12];
    const float* n2_b = (const float*)d_in[13];
    const float* n3_g = (const float*)d_in[14];
    const float* n3_b = (const float*)d_in[15];
    const float* mlp_w1 = (const float*)d_in[16];
    const float* mlp_b1 = (const float*)d_in[17];
    const float* mlp_w2 = (const float*)d_in[18];
    const float* mlp_b2 = (const float*)d_in[19];
    const float* hw1 = (const float*)d_in[20];
    const float* hb1 = (const float*)d_in[21];
    const float* hw2 = (const float*)d_in[22];
    const float* hb2 = (const float*)d_in[23];
    const float* hw3 = (const float*)d_in[24];
    const float* hb3 = (const float*)d_in[25];
    float* out = (float*)d_out;

    int E = in_sizes[1] / 2;

    float *p_x, *p_agg, *p_t1, *p_t2, *p_h1, *p_h2;
    __nv_bfloat16 *p_qb, *p_kb, *p_vtb;
    cudaGetSymbolAddress((void**)&p_x,  g_x);
    cudaGetSymbolAddress((void**)&p_agg, g_agg);
    cudaGetSymbolAddress((void**)&p_t1, g_t1);
    cudaGetSymbolAddress((void**)&p_t2, g_t2);
    cudaGetSymbolAddress((void**)&p_h1, g_h1);
    cudaGetSymbolAddress((void**)&p_h2, g_h2);
    cudaGetSymbolAddress((void**)&p_qb, g_qb);
    cudaGetSymbolAddress((void**)&p_kb, g_kb);
    cudaGetSymbolAddress((void**)&p_vtb, g_vtb);

    const int NC4 = NN * CC / 4;

    copy_kernel<<<(NC4 + 255) / 256, 256>>>(x_in, p_x, NC4);

    for (int i = 0; i < LL; i++) {
        const float* gw1 = gin_w1 + (long)i * CC * CC;
        const float* gb1 = gin_b1 + (long)i * CC;
        const float* gw2 = gin_w2 + (long)i * CC * CC;
        const float* gb2 = gin_b2 + (long)i * CC;
        const float* aiw = attn_in_w + (long)i * 3 * CC * CC;
        const float* aib = attn_in_b + (long)i * 3 * CC;
        const float* aow = attn_o_w + (long)i * CC * CC;
        const float* aob = attn_o_b + (long)i * CC;
        const float* mw1 = mlp_w1 + (long)i * 2 * CC * CC;
        const float* mb1 = mlp_b1 + (long)i * 2 * CC;
        const float* mw2 = mlp_w2 + (long)i * CC * 2 * CC;
        const float* mb2 = mlp_b2 + (long)i * CC;

        // ---- GIN branch ----
        copy_kernel<<<(NC4 + 255) / 256, 256>>>(p_x, p_agg, NC4);
        long nsc = (long)E * CC;
        scatter_kernel<<<(int)((nsc + 255) / 256), 256>>>(edge, p_x, p_agg, E);
        launch_gemm(p_agg, gw1, gb1, p_t1, NN, CC, CC, true);
        launch_gemm(p_t1, gw2, gb2, p_t2, NN, CC, CC, false);
        bn_kernel<<<CC, 256>>>(p_t2, p_x, n1_g + i * CC, n1_b + i * CC, p_h1);

        // ---- attention branch (mma.sync flash) ----
        launch_gemm(p_x, aiw, aib, p_t1, NN, 3 * CC, CC, false);
        qkv_convert<<<NN * CC / 256, 256>>>(p_t1, p_qb, p_kb, p_vtb);
        mma_attn<<<dim3(NN / 128, HEADS), 256>>>(p_qb, p_kb, p_vtb, p_agg);
        launch_gemm(p_agg, aow, aob, p_t2, NN, CC, CC, false);
        bn_kernel<<<CC, 256>>>(p_t2, p_x, n2_g + i * CC, n2_b + i * CC, p_h2);

        // ---- merge + MLP ----
        add_kernel<<<(NC4 + 255) / 256, 256>>>(p_h1, p_h2, p_t2, NC4);
        launch_gemm(p_t2, mw1, mb1, p_t1, NN, 2 * CC, CC, true);
        launch_gemm(p_t1, mw2, mb2, p_agg, NN, CC, 2 * CC, false);
        bn_kernel<<<CC, 256>>>(p_t2, p_agg, n3_g + i * CC, n3_b + i * CC, p_x);
    }

    // ---- head MLP ----
    launch_gemm(p_x, hw1, hb1, p_t1, NN, CC / 2, CC, true);
    launch_gemm(p_t1, hw2, hb2, p_t2, NN, CC / 4, CC / 2, true);
    head_final<<<(NN + 255) / 256, 256>>>(p_t2, hw3, hb3, out);
}

// round 4
// speedup vs baseline: 5.6493x; 1.1693x over previous
#include <cuda_runtime.h>
#include <cuda_bf16.h>
#include <cstdint>

#define NN 4096
#define CC 128
#define LL 4
#define HEADS 4
#define BN_EPS 1e-5f
#define EMAX 262144

// ---------------- scratch (static device globals; no allocation) ----------------
__device__ float g_x  [NN * CC];
__device__ float g_agg[NN * CC];
__device__ float g_t1 [NN * 384];
__device__ float g_t2 [NN * CC];
__device__ float g_h1 [NN * CC];
__device__ float g_h2 [NN * CC];
__device__ float g_bnsum[2 * CC];
__device__ int   g_deg[NN + 1];
__device__ int   g_cur[NN];
__device__ int   g_csr[EMAX];
__device__ __nv_bfloat16 g_qb [HEADS * NN * 32];
__device__ __nv_bfloat16 g_kb [HEADS * NN * 32];
__device__ __nv_bfloat16 g_vtb[HEADS * 32 * NN];

// ---------------- mma.sync helpers ----------------
__device__ __forceinline__ void mma_bf16(float* d, uint32_t a0, uint32_t a1, uint32_t a2,
                                         uint32_t a3, uint32_t b0, uint32_t b1) {
    asm volatile(
        "mma.sync.aligned.m16n8k16.row.col.f32.bf16.bf16.f32 "
        "{%0,%1,%2,%3}, {%4,%5,%6,%7}, {%8,%9}, {%0,%1,%2,%3};"
        : "+f"(d[0]), "+f"(d[1]), "+f"(d[2]), "+f"(d[3])
        : "r"(a0), "r"(a1), "r"(a2), "r"(a3), "r"(b0), "r"(b1));
}
__device__ __forceinline__ float fast_exp2(float x) {
    float y; asm("ex2.approx.ftz.f32 %0, %1;" : "=f"(y) : "f"(x)); return y;
}
__device__ __forceinline__ uint32_t pack_bf16(float lo, float hi) {
    uint32_t r; asm("cvt.rn.bf16x2.f32 %0, %1, %2;" : "=r"(r) : "f"(hi), "f"(lo)); return r;
}

// ---------------- misc ----------------
__global__ void copy_kernel(const float* __restrict__ a, float* __restrict__ o, int n4) {
    int i = blockIdx.x * blockDim.x + threadIdx.x;
    if (i < n4) ((float4*)o)[i] = ((const float4*)a)[i];
}

// ---------------- CSR build ----------------
__global__ void hist_kernel(const int* __restrict__ ei, int E) {
    int e = blockIdx.x * blockDim.x + threadIdx.x;
    if (e < E) atomicAdd(&g_deg[ei[E + e] + 1], 1);
}

__global__ void scan_kernel() {
    // inclusive scan over g_deg[0..NN]; g_deg[0]=0, g_deg[i+1]=deg(i) pre-scan.
    __shared__ int part[1024];
    int t = threadIdx.x;
    int base = t * 4;
    int x0 = g_deg[base], x1 = g_deg[base + 1], x2 = g_deg[base + 2], x3 = g_deg[base + 3];
    x1 += x0; x2 += x1; x3 += x2;
    part[t] = x3;
    __syncthreads();
    for (int off = 1; off < 1024; off <<= 1) {
        int v = (t >= off) ? part[t - off] : 0;
        __syncthreads();
        part[t] += v;
        __syncthreads();
    }
    int add = (t > 0) ? part[t - 1] : 0;
    int v0 = x0 + add, v1 = x1 + add, v2 = x2 + add, v3 = x3 + add;
    g_deg[base] = v0; g_deg[base + 1] = v1; g_deg[base + 2] = v2; g_deg[base + 3] = v3;
    g_cur[base] = v0; g_cur[base + 1] = v1; g_cur[base + 2] = v2; g_cur[base + 3] = v3;
    __syncthreads();
    if (t == 0) g_deg[NN] += g_deg[NN - 1];   // tail element (raw deg of node NN-1)
}

__global__ void fill_kernel(const int* __restrict__ ei, int E) {
    int e = blockIdx.x * blockDim.x + threadIdx.x;
    if (e >= E) return;
    int s = ei[e], d = ei[E + e];
    int pos = atomicAdd(&g_cur[d], 1);
    g_csr[pos] = s;
}

// ---------------- GIN gather: agg[n] = x[n] + sum_{j in N(n)} x[src_j] ----------------
__global__ __launch_bounds__(256) void gather_kernel(const float* __restrict__ x,
                                                     float* __restrict__ agg) {
    int wg = (blockIdx.x * 256 + threadIdx.x) >> 5;   // node
    int lane = threadIdx.x & 31;
    if (wg >= NN) return;
    int beg = g_deg[wg], end = g_deg[wg + 1];
    float4 acc = *(const float4*)&x[(long)wg * CC + lane * 4];
    for (int j = beg; j < end; j++) {
        int s = g_csr[j];
        float4 v = *(const float4*)&x[(long)s * CC + lane * 4];
        acc.x += v.x; acc.y += v.y; acc.z += v.z; acc.w += v.w;
    }
    *(float4*)&agg[(long)wg * CC + lane * 4] = acc;
}

// ---------------- SGEMM 64x64 tile, 256 threads, K chunks of 64 ----------------
// C[M,N] = act((A[+A2])[M,K] @ B[N,K]^T + bias). M%64==0, K%64==0, N%4==0.
template <bool RELU, bool ADD2>
__global__ __launch_bounds__(256) void gemm_v3(const float* __restrict__ A,
        const float* __restrict__ A2, const float* __restrict__ B,
        const float* __restrict__ bias, float* __restrict__ C, int M, int N, int K) {
    __shared__ float As[64][72];
    __shared__ float Bs[64][72];
    int tid = threadIdx.x;
    int bm = blockIdx.y * 64, bn = blockIdx.x * 64;
    int ty = tid >> 4, tx = tid & 15;
    int lrow = tid >> 2, lc4 = tid & 3;
    float acc[4][4] = {};

    for (int k0 = 0; k0 < K; k0 += 64) {
#pragma unroll
        for (int it = 0; it < 4; it++) {
            int c4 = lc4 + it * 4;                 // 0..15 -> k-offset c4*4
            const float* pa = &A[(long)(bm + lrow) * K + k0 + c4 * 4];
            float4 v = *(const float4*)pa;
            if (ADD2) {
                float4 w = *(const float4*)&A2[(long)(bm + lrow) * K + k0 + c4 * 4];
                v.x += w.x; v.y += w.y; v.z += w.z; v.w += w.w;
            }
            As[c4 * 4 + 0][lrow] = v.x; As[c4 * 4 + 1][lrow] = v.y;
            As[c4 * 4 + 2][lrow] = v.z; As[c4 * 4 + 3][lrow] = v.w;
            int brow = bn + lrow;
            float4 bv = make_float4(0.f, 0.f, 0.f, 0.f);
            if (brow < N) bv = *(const float4*)&B[(long)brow * K + k0 + c4 * 4];
            Bs[c4 * 4 + 0][lrow] = bv.x; Bs[c4 * 4 + 1][lrow] = bv.y;
            Bs[c4 * 4 + 2][lrow] = bv.z; Bs[c4 * 4 + 3][lrow] = bv.w;
        }
        __syncthreads();
#pragma unroll 8
        for (int kk = 0; kk < 64; kk++) {
            float4 a4 = *(const float4*)&As[kk][ty * 4];
            float4 b4 = *(const float4*)&Bs[kk][tx * 4];
            float a[4] = {a4.x, a4.y, a4.z, a4.w};
            float b[4] = {b4.x, b4.y, b4.z, b4.w};
#pragma unroll
            for (int i = 0; i < 4; i++)
#pragma unroll
                for (int j = 0; j < 4; j++) acc[i][j] = fmaf(a[i], b[j], acc[i][j]);
        }
        __syncthreads();
    }
    int colb = bn + tx * 4;
    if (colb + 3 < N) {
        float4 bb = *(const float4*)&bias[colb];
#pragma unroll
        for (int i = 0; i < 4; i++) {
            int row = bm + ty * 4 + i;
            float4 o = make_float4(acc[i][0] + bb.x, acc[i][1] + bb.y,
                                   acc[i][2] + bb.z, acc[i][3] + bb.w);
            if (RELU) {
                o.x = fmaxf(o.x, 0.f); o.y = fmaxf(o.y, 0.f);
                o.z = fmaxf(o.z, 0.f); o.w = fmaxf(o.w, 0.f);
            }
            *(float4*)&C[(long)row * N + colb] = o;
        }
    }
}

// ---------------- BatchNorm: two-pass, coalesced ----------------
// sums[c] = col sum, sums[CC+c] = col sumsq  (pre-zeroed)
template <int NIN>
__global__ __launch_bounds__(256) void bn_reduce(const float* __restrict__ in1,
        const float* __restrict__ in2, const float* __restrict__ in3,
        float* __restrict__ sums) {
    __shared__ float shs[8][128];
    __shared__ float shq[8][128];
    int tx = threadIdx.x & 31, ty = threadIdx.x >> 5;
    float4 s = make_float4(0.f, 0.f, 0.f, 0.f);
    float4 q = make_float4(0.f, 0.f, 0.f, 0.f);
    for (int r = blockIdx.x * 8 + ty; r < NN; r += 64 * 8) {
        float4 v = ((const float4*)in1)[r * 32 + tx];
        if (NIN >= 2) {
            float4 w = ((const float4*)in2)[r * 32 + tx];
            v.x += w.x; v.y += w.y; v.z += w.z; v.w += w.w;
        }
        if (NIN >= 3) {
            float4 w = ((const float4*)in3)[r * 32 + tx];
            v.x += w.x; v.y += w.y; v.z += w.z; v.w += w.w;
        }
        s.x += v.x; s.y += v.y; s.z += v.z; s.w += v.w;
        q.x += v.x * v.x; q.y += v.y * v.y; q.z += v.z * v.z; q.w += v.w * v.w;
    }
    shs[ty][tx * 4 + 0] = s.x; shs[ty][tx * 4 + 1] = s.y;
    shs[ty][tx * 4 + 2] = s.z; shs[ty][tx * 4 + 3] = s.w;
    shq[ty][tx * 4 + 0] = q.x; shq[ty][tx * 4 + 1] = q.y;
    shq[ty][tx * 4 + 2] = q.z; shq[ty][tx * 4 + 3] = q.w;
    __syncthreads();
    int c = threadIdx.x;
    if (c < 128) {
        float ts = 0.f, tq = 0.f;
#pragma unroll
        for (int k = 0; k < 8; k++) { ts += shs[k][c]; tq += shq[k][c]; }
        atomicAdd(&sums[c], ts);
        atomicAdd(&sums[CC + c], tq);
    }
}

template <int NIN>
__global__ __launch_bounds__(256) void bn_apply(const float* __restrict__ in1,
        const float* __restrict__ in2, const float* __restrict__ in3,
        const float* __restrict__ g, const float* __restrict__ b,
        const float* __restrict__ sums, float* __restrict__ out) {
    int i = blockIdx.x * 256 + threadIdx.x;      // over NN*32 float4s
    if (i >= NN * 32) return;
    int c4 = i & 31;
    float4 v = ((const float4*)in1)[i];
    if (NIN >= 2) {
        float4 w = ((const float4*)in2)[i];
        v.x += w.x; v.y += w.y; v.z += w.z; v.w += w.w;
    }
    if (NIN >= 3) {
        float4 w = ((const float4*)in3)[i];
        v.x += w.x; v.y += w.y; v.z += w.z; v.w += w.w;
    }
    float o[4] = {v.x, v.y, v.z, v.w};
#pragma unroll
    for (int k = 0; k < 4; k++) {
        int c = c4 * 4 + k;
        float mean = sums[c] * (1.f / NN);
        float var  = sums[CC + c] * (1.f / NN) - mean * mean;
        float sc   = rsqrtf(var + BN_EPS) * g[c];
        o[k] = (o[k] - mean) * sc + b[c];
    }
    ((float4*)out)[i] = make_float4(o[0], o[1], o[2], o[3]);
}

// ---------------- qkv fp32 -> bf16 Q/K/V^T ----------------
__global__ void qkv_convert(const float* __restrict__ qkv, __nv_bfloat16* __restrict__ qb,
                            __nv_bfloat16* __restrict__ kb, __nv_bfloat16* __restrict__ vtb) {
    int id = blockIdx.x * 256 + threadIdx.x;
    int n = id >> 7, c = id & 127;
    int h = c >> 5, d = c & 31;
    float q = qkv[n * 384 + c];
    float k = qkv[n * 384 + 128 + c];
    float v = qkv[n * 384 + 256 + c];
    qb [((h << 12) + n) * 32 + d] = __float2bfloat16(q);
    kb [((h << 12) + n) * 32 + d] = __float2bfloat16(k);
    vtb[((h * 32 + d) << 12) + n] = __float2bfloat16(v);
}

// ---------------- mma.sync flash attention ----------------
#define EXP2_SCALE 0.25503480f
#define QK_STRIDE 40
#define VT_STRIDE 136

__global__ __launch_bounds__(256, 1) void mma_attn(const __nv_bfloat16* __restrict__ qb,
        const __nv_bfloat16* __restrict__ kb, const __nv_bfloat16* __restrict__ vtb,
        float* __restrict__ out) {
    __shared__ uint16_t Qs[128 * QK_STRIDE];
    __shared__ uint16_t Ks[128 * QK_STRIDE];
    __shared__ uint16_t Vts[32 * VT_STRIDE];

    const int tid = threadIdx.x;
    const int wid = tid >> 5, lane = tid & 31;
    const int gid = lane >> 2, tig = lane & 3;
    const int h = blockIdx.y;
    const int qbase = blockIdx.x * 128;
    const int r0 = wid * 16;

    const uint16_t* Qg = (const uint16_t*)(qb + ((long)h * NN + qbase) * 32);
#pragma unroll
    for (int it = 0; it < 2; it++) {
        int i = tid + it * 256;
        int row = i >> 2, seg = i & 3;
        *(uint4*)&Qs[row * QK_STRIDE + seg * 8] = *(const uint4*)&Qg[row * 32 + seg * 8];
    }
    __syncthreads();

    uint32_t aq[2][4];
#pragma unroll
    for (int t = 0; t < 2; t++) {
        int k = t * 16 + tig * 2;
        aq[t][0] = *(const uint32_t*)&Qs[(r0 + gid    ) * QK_STRIDE + k    ];
        aq[t][1] = *(const uint32_t*)&Qs[(r0 + gid + 8) * QK_STRIDE + k    ];
        aq[t][2] = *(const uint32_t*)&Qs[(r0 + gid    ) * QK_STRIDE + k + 8];
        aq[t][3] = *(const uint32_t*)&Qs[(r0 + gid + 8) * QK_STRIDE + k + 8];
    }

    float oacc[4][4] = {};
    float rs0 = 0.f, rs1 = 0.f;

    for (int kt = 0; kt < NN / 128; kt++) {
        const int kb0 = kt * 128;
        __syncthreads();
        const uint16_t* Kg = (const uint16_t*)(kb + ((long)h * NN + kb0) * 32);
#pragma unroll
        for (int it = 0; it < 2; it++) {
            int i = tid + it * 256;
            int row = i >> 2, seg = i & 3;
            *(uint4*)&Ks[row * QK_STRIDE + seg * 8] = *(const uint4*)&Kg[row * 32 + seg * 8];
        }
        const uint16_t* Vg = (const uint16_t*)(vtb + ((long)h * 32) * NN + kb0);
#pragma unroll
        for (int it = 0; it < 2; it++) {
            int i = tid + it * 256;
            int d = i >> 4, seg = i & 15;
            *(uint4*)&Vts[d * VT_STRIDE + seg * 8] = *(const uint4*)&Vg[(long)d * NN + seg * 8];
        }
        __syncthreads();

        float sacc[16][4];
#pragma unroll
        for (int j = 0; j < 16; j++) { sacc[j][0] = sacc[j][1] = sacc[j][2] = sacc[j][3] = 0.f; }
#pragma unroll
        for (int j = 0; j < 16; j++) {
#pragma unroll
            for (int t = 0; t < 2; t++) {
                int k = t * 16 + tig * 2;
                uint32_t b0 = *(const uint32_t*)&Ks[(8 * j + gid) * QK_STRIDE + k    ];
                uint32_t b1 = *(const uint32_t*)&Ks[(8 * j + gid) * QK_STRIDE + k + 8];
                mma_bf16(sacc[j], aq[t][0], aq[t][1], aq[t][2], aq[t][3], b0, b1);
            }
        }

        uint32_t pf[16][2];
#pragma unroll
        for (int j = 0; j < 16; j++) {
            float p0 = fast_exp2(sacc[j][0] * EXP2_SCALE);
            float p1 = fast_exp2(sacc[j][1] * EXP2_SCALE);
            float p2 = fast_exp2(sacc[j][2] * EXP2_SCALE);
            float p3 = fast_exp2(sacc[j][3] * EXP2_SCALE);
            rs0 += p0 + p1;
            rs1 += p2 + p3;
            pf[j][0] = pack_bf16(p0, p1);
            pf[j][1] = pack_bf16(p2, p3);
        }

#pragma unroll
        for (int t = 0; t < 8; t++) {
            uint32_t a0 = pf[2 * t][0], a1 = pf[2 * t][1];
            uint32_t a2 = pf[2 * t + 1][0], a3 = pf[2 * t + 1][1];
            int k = t * 16 + tig * 2;
#pragma unroll
            for (int n = 0; n < 4; n++) {
                uint32_t b0 = *(const uint32_t*)&Vts[(8 * n + gid) * VT_STRIDE + k    ];
                uint32_t b1 = *(const uint32_t*)&Vts[(8 * n + gid) * VT_STRIDE + k + 8];
                mma_bf16(oacc[n], a0, a1, a2, a3, b0, b1);
            }
        }
    }

    rs0 += __shfl_xor_sync(0xFFFFFFFF, rs0, 1);
    rs0 += __shfl_xor_sync(0xFFFFFFFF, rs0, 2);
    rs1 += __shfl_xor_sync(0xFFFFFFFF, rs1, 1);
    rs1 += __shfl_xor_sync(0xFFFFFFFF, rs1, 2);
    float inv0 = 1.f / rs0, inv1 = 1.f / rs1;

    int rowA = qbase + r0 + gid, rowB = rowA + 8;
    float* poA = out + (long)rowA * CC + h * 32 + tig * 2;
    float* poB = out + (long)rowB * CC + h * 32 + tig * 2;
#pragma unroll
    for (int n = 0; n < 4; n++) {
        *(float2*)(poA + n * 8) = make_float2(oacc[n][0] * inv0, oacc[n][1] * inv0);
        *(float2*)(poB + n * 8) = make_float2(oacc[n][2] * inv1, oacc[n][3] * inv1);
    }
}

// ---------------- final head dot ----------------
__global__ void head_final(const float* __restrict__ t32, const float* __restrict__ w,
                           const float* __restrict__ b, float* __restrict__ out) {
    int n = blockIdx.x * blockDim.x + threadIdx.x;
    if (n >= NN) return;
    float s = b[0];
#pragma unroll
    for (int k = 0; k < 32; k++) s = fmaf(t32[n * 32 + k], w[k], s);
    out[n] = s;
}

// ---------------- host orchestration ----------------
static void launch_gemm(const float* A, const float* B, const float* bias, float* C,
                        int M, int N, int K, bool relu) {
    dim3 grid((N + 63) / 64, M / 64);
    if (relu) gemm_v3<true, false><<<grid, 256>>>(A, nullptr, B, bias, C, M, N, K);
    else      gemm_v3<false, false><<<grid, 256>>>(A, nullptr, B, bias, C, M, N, K);
}
static void launch_gemm_add2(const float* A, const float* A2, const float* B,
                             const float* bias, float* C, int M, int N, int K, bool relu) {
    dim3 grid((N + 63) / 64, M / 64);
    if (relu) gemm_v3<true, true><<<grid, 256>>>(A, A2, B, bias, C, M, N, K);
    else      gemm_v3<false, true><<<grid, 256>>>(A, A2, B, bias, C, M, N, K);
}

static void launch_bn2(const float* in1, const float* in2, const float* g, const float* b,
                       float* sums, float* out) {
    cudaMemsetAsync(sums, 0, 2 * CC * sizeof(float));
    bn_reduce<2><<<64, 256>>>(in1, in2, nullptr, sums);
    bn_apply<2><<<NN * 32 / 256, 256>>>(in1, in2, nullptr, g, b, sums, out);
}
static void launch_bn3(const float* in1, const float* in2, const float* in3, const float* g,
                       const float* b, float* sums, float* out) {
    cudaMemsetAsync(sums, 0, 2 * CC * sizeof(float));
    bn_reduce<3><<<64, 256>>>(in1, in2, in3, sums);
    bn_apply<3><<<NN * 32 / 256, 256>>>(in1, in2, in3, g, b, sums, out);
}

extern "C" void kernel_launch(void* const* d_in, const int* in_sizes, int n_in,
                              void* d_out, int out_size) {
    const float* x_in      = (const float*)d_in[0];
    const int*   edge      = (const int*)  d_in[1];
    const float* gin_w1    = (const float*)d_in[2];
    const float* gin_b1    = (const float*)d_in[3];
    const float* gin_w2    = (const float*)d_in[4];
    const float* gin_b2    = (const float*)d_in[5];
    const float* attn_in_w = (const float*)d_in[6];
    const float* attn_in_b = (const float*)d_in[7];
    const float* attn_o_w  = (const float*)d_in[8];
    const float* attn_o_b  = (const float*)d_in[9];
    const float* n1_g = (const float*)d_in[10];
    const float* n1_b = (const float*)d_in[11];
    const float* n2_g = (const float*)d_in[12];
    const float* n2_b = (const float*)d_in[13];
    const float* n3_g = (const float*)d_in[14];
    const float* n3_b = (const float*)d_in[15];
    const float* mlp_w1 = (const float*)d_in[16];
    const float* mlp_b1 = (const float*)d_in[17];
    const float* mlp_w2 = (const float*)d_in[18];
    const float* mlp_b2 = (const float*)d_in[19];
    const float* hw1 = (const float*)d_in[20];
    const float* hb1 = (const float*)d_in[21];
    const float* hw2 = (const float*)d_in[22];
    const float* hb2 = (const float*)d_in[23];
    const float* hw3 = (const float*)d_in[24];
    const float* hb3 = (const float*)d_in[25];
    float* out = (float*)d_out;

    int E = in_sizes[1] / 2;

    float *p_x, *p_agg, *p_t1, *p_t2, *p_h1, *p_h2, *p_bnsum;
    int *p_deg;
    __nv_bfloat16 *p_qb, *p_kb, *p_vtb;
    cudaGetSymbolAddress((void**)&p_x,  g_x);
    cudaGetSymbolAddress((void**)&p_agg, g_agg);
    cudaGetSymbolAddress((void**)&p_t1, g_t1);
    cudaGetSymbolAddress((void**)&p_t2, g_t2);
    cudaGetSymbolAddress((void**)&p_h1, g_h1);
    cudaGetSymbolAddress((void**)&p_h2, g_h2);
    cudaGetSymbolAddress((void**)&p_bnsum, g_bnsum);
    cudaGetSymbolAddress((void**)&p_deg, g_deg);
    cudaGetSymbolAddress((void**)&p_qb, g_qb);
    cudaGetSymbolAddress((void**)&p_kb, g_kb);
    cudaGetSymbolAddress((void**)&p_vtb, g_vtb);

    const int NC4 = NN * CC / 4;

    // ---- CSR build (reused across all 4 layers) ----
    cudaMemsetAsync(p_deg, 0, (NN + 1) * sizeof(int));
    hist_kernel<<<(E + 255) / 256, 256>>>(edge, E);
    scan_kernel<<<1, 1024>>>();
    fill_kernel<<<(E + 255) / 256, 256>>>(edge, E);

    copy_kernel<<<(NC4 + 255) / 256, 256>>>(x_in, p_x, NC4);

    for (int i = 0; i < LL; i++) {
        const float* gw1 = gin_w1 + (long)i * CC * CC;
        const float* gb1 = gin_b1 + (long)i * CC;
        const float* gw2 = gin_w2 + (long)i * CC * CC;
        const float* gb2 = gin_b2 + (long)i * CC;
        const float* aiw = attn_in_w + (long)i * 3 * CC * CC;
        const float* aib = attn_in_b + (long)i * 3 * CC;
        const float* aow = attn_o_w + (long)i * CC * CC;
        const float* aob = attn_o_b + (long)i * CC;
        const float* mw1 = mlp_w1 + (long)i * 2 * CC * CC;
        const float* mb1 = mlp_b1 + (long)i * 2 * CC;
        const float* mw2 = mlp_w2 + (long)i * CC * 2 * CC;
        const float* mb2 = mlp_b2 + (long)i * CC;

        // ---- GIN branch ----
        gather_kernel<<<NN / 8, 256>>>(p_x, p_agg);
        launch_gemm(p_agg, gw1, gb1, p_t1, NN, CC, CC, true);
        launch_gemm(p_t1, gw2, gb2, p_t2, NN, CC, CC, false);
        launch_bn2(p_t2, p_x, n1_g + i * CC, n1_b + i * CC, p_bnsum, p_h1);

        // ---- attention branch ----
        launch_gemm(p_x, aiw, aib, p_t1, NN, 3 * CC, CC, false);
        qkv_convert<<<NN * CC / 256, 256>>>(p_t1, p_qb, p_kb, p_vtb);
        mma_attn<<<dim3(NN / 128, HEADS), 256>>>(p_qb, p_kb, p_vtb, p_agg);
        launch_gemm(p_agg, aow, aob, p_t2, NN, CC, CC, false);
        launch_bn2(p_t2, p_x, n2_g + i * CC, n2_b + i * CC, p_bnsum, p_h2);

        // ---- MLP (h = h1 + h2 fused into A-load; bn3 over h1+h2+m) ----
        launch_gemm_add2(p_h1, p_h2, mw1, mb1, p_t1, NN, 2 * CC, CC, true);
        launch_gemm(p_t1, mw2, mb2, p_t2, NN, CC, 2 * CC, false);
        launch_bn3(p_h1, p_h2, p_t2, n3_g + i * CC, n3_b + i * CC, p_bnsum, p_x);
    }

    // ---- head MLP ----
    launch_gemm(p_x, hw1, hb1, p_t1, NN, CC / 2, CC, true);
    launch_gemm(p_t1, hw2, hb2, p_t2, NN, CC / 4, CC / 2, true);
    head_final<<<(NN + 255) / 256, 256>>>(p_t2, hw3, hb3, out);
}

// round 5
// speedup vs baseline: 6.8820x; 1.2182x over previous
#include <cuda_runtime.h>
#include <cuda_bf16.h>
#include <cstdint>

#define NN 4096
#define CC 128
#define LL 4
#define HEADS 4
#define BN_EPS 1e-5f
#define EMAX 262144

// ---------------- scratch (static device globals; no allocation) ----------------
__device__ float g_x  [NN * CC];
__device__ float g_agg[NN * CC];
__device__ float g_t1 [NN * 384];
__device__ float g_t2 [NN * CC];
__device__ float g_h1 [NN * CC];
__device__ float g_h2 [NN * CC];
__device__ float g_bnsum[2 * CC];
__device__ int   g_deg[NN + 1];
__device__ int   g_cur[NN];
__device__ int   g_csr[EMAX];
__device__ __nv_bfloat16 g_qb [HEADS * NN * 32];
__device__ __nv_bfloat16 g_kb [HEADS * NN * 32];
__device__ __nv_bfloat16 g_vtb[HEADS * 32 * NN];

// concatenated hi/lo bf16 weights
#define WOFF_GIN1 0
#define WOFF_GIN2 65536
#define WOFF_AIN  131072
#define WOFF_AOUT 327680
#define WOFF_MW1  393216
#define WOFF_MW2  524288
#define WOFF_HW1  655360
#define WOFF_HW2  663552
#define WOFF_HW3  665600
#define WTOTAL    665632
__device__ __nv_bfloat16 g_whi[WTOTAL];
__device__ __nv_bfloat16 g_wlo[WTOTAL];

// ---------------- mma.sync helpers ----------------
__device__ __forceinline__ void mma_bf16(float* d, uint32_t a0, uint32_t a1, uint32_t a2,
                                         uint32_t a3, uint32_t b0, uint32_t b1) {
    asm volatile(
        "mma.sync.aligned.m16n8k16.row.col.f32.bf16.bf16.f32 "
        "{%0,%1,%2,%3}, {%4,%5,%6,%7}, {%8,%9}, {%0,%1,%2,%3};"
        : "+f"(d[0]), "+f"(d[1]), "+f"(d[2]), "+f"(d[3])
        : "r"(a0), "r"(a1), "r"(a2), "r"(a3), "r"(b0), "r"(b1));
}
__device__ __forceinline__ float fast_exp2(float x) {
    float y; asm("ex2.approx.ftz.f32 %0, %1;" : "=f"(y) : "f"(x)); return y;
}
__device__ __forceinline__ uint32_t pack_bf16(float lo, float hi) {
    uint32_t r; asm("cvt.rn.bf16x2.f32 %0, %1, %2;" : "=r"(r) : "f"(hi), "f"(lo)); return r;
}
// split f32 pair into hi-u32 and lo-u32 (bf16x2 each)
__device__ __forceinline__ void split2(float x, float y, uint32_t& hi, uint32_t& lo) {
    __nv_bfloat16 hx = __float2bfloat16(x), hy = __float2bfloat16(y);
    float lx = x - __bfloat162float(hx), ly = y - __bfloat162float(hy);
    hi = pack_bf16(__bfloat162float(hx), __bfloat162float(hy));
    lo = pack_bf16(lx, ly);
}

// ---------------- misc ----------------
__global__ void copy_kernel(const float* __restrict__ a, float* __restrict__ o, int n4) {
    int i = blockIdx.x * blockDim.x + threadIdx.x;
    if (i < n4) ((float4*)o)[i] = ((const float4*)a)[i];
}

// ---------------- weight hi/lo conversion (once per launch) ----------------
__global__ void conv_w(const float* __restrict__ w_gin1, const float* __restrict__ w_gin2,
                       const float* __restrict__ w_ain,  const float* __restrict__ w_aout,
                       const float* __restrict__ w_m1,   const float* __restrict__ w_m2,
                       const float* __restrict__ w_h1,   const float* __restrict__ w_h2,
                       const float* __restrict__ w_h3) {
    int id = blockIdx.x * 256 + threadIdx.x;
    if (id >= WTOTAL) return;
    const float* src; int off;
    if      (id < WOFF_GIN2) { src = w_gin1; off = id; }
    else if (id < WOFF_AIN)  { src = w_gin2; off = id - WOFF_GIN2; }
    else if (id < WOFF_AOUT) { src = w_ain;  off = id - WOFF_AIN; }
    else if (id < WOFF_MW1)  { src = w_aout; off = id - WOFF_AOUT; }
    else if (id < WOFF_MW2)  { src = w_m1;   off = id - WOFF_MW1; }
    else if (id < WOFF_HW1)  { src = w_m2;   off = id - WOFF_MW2; }
    else if (id < WOFF_HW2)  { src = w_h1;   off = id - WOFF_HW1; }
    else if (id < WOFF_HW3)  { src = w_h2;   off = id - WOFF_HW2; }
    else                     { src = w_h3;   off = id - WOFF_HW3; }
    float v = src[off];
    __nv_bfloat16 h = __float2bfloat16(v);
    g_whi[id] = h;
    g_wlo[id] = __float2bfloat16(v - __bfloat162float(h));
}

// ---------------- CSR build ----------------
__global__ void hist_kernel(const int* __restrict__ ei, int E) {
    int e = blockIdx.x * blockDim.x + threadIdx.x;
    if (e < E) atomicAdd(&g_deg[ei[E + e] + 1], 1);
}

__global__ void scan_kernel() {
    __shared__ int part[1024];
    int t = threadIdx.x;
    int base = t * 4;
    int x0 = g_deg[base], x1 = g_deg[base + 1], x2 = g_deg[base + 2], x3 = g_deg[base + 3];
    x1 += x0; x2 += x1; x3 += x2;
    part[t] = x3;
    __syncthreads();
    for (int off = 1; off < 1024; off <<= 1) {
        int v = (t >= off) ? part[t - off] : 0;
        __syncthreads();
        part[t] += v;
        __syncthreads();
    }
    int add = (t > 0) ? part[t - 1] : 0;
    int v0 = x0 + add, v1 = x1 + add, v2 = x2 + add, v3 = x3 + add;
    g_deg[base] = v0; g_deg[base + 1] = v1; g_deg[base + 2] = v2; g_deg[base + 3] = v3;
    g_cur[base] = v0; g_cur[base + 1] = v1; g_cur[base + 2] = v2; g_cur[base + 3] = v3;
    __syncthreads();
    if (t == 0) g_deg[NN] += g_deg[NN - 1];
}

__global__ void fill_kernel(const int* __restrict__ ei, int E) {
    int e = blockIdx.x * blockDim.x + threadIdx.x;
    if (e >= E) return;
    int s = ei[e], d = ei[E + e];
    int pos = atomicAdd(&g_cur[d], 1);
    g_csr[pos] = s;
}

// ---------------- GIN gather ----------------
__global__ __launch_bounds__(256) void gather_kernel(const float* __restrict__ x,
                                                     float* __restrict__ agg) {
    int wg = (blockIdx.x * 256 + threadIdx.x) >> 5;
    int lane = threadIdx.x & 31;
    if (wg >= NN) return;
    int beg = g_deg[wg], end = g_deg[wg + 1];
    float4 acc = *(const float4*)&x[(long)wg * CC + lane * 4];
    for (int j = beg; j < end; j++) {
        int s = g_csr[j];
        float4 v = *(const float4*)&x[(long)s * CC + lane * 4];
        acc.x += v.x; acc.y += v.y; acc.z += v.z; acc.w += v.w;
    }
    *(float4*)&agg[(long)wg * CC + lane * 4] = acc;
}

// ---------------- tensor-core GEMM: C = act((A[+A2]) @ B^T + bias) ----------------
// A fp32 [M,K] split to bf16 hi/lo on load; B pre-split bf16 [N,K].
// 3-MMA split: hi*hi + hi*lo + lo*hi. Tile 64x64, BK=32, 8 warps.
// QKV=true: N=384, writes q/k/v^T bf16 buffers instead of C.
#define AST 40
template <bool RELU, bool ADD2, bool QKV>
__global__ __launch_bounds__(256) void gemm_tc(const float* __restrict__ A,
        const float* __restrict__ A2,
        const __nv_bfloat16* __restrict__ Bh, const __nv_bfloat16* __restrict__ Bl,
        const float* __restrict__ bias, float* __restrict__ C,
        __nv_bfloat16* __restrict__ qb, __nv_bfloat16* __restrict__ kbuf,
        __nv_bfloat16* __restrict__ vtb, int M, int N, int K) {
    __shared__ uint16_t Ahs[64 * AST], Als[64 * AST];
    __shared__ uint16_t Bhs[64 * AST], Bls[64 * AST];
    const int tid = threadIdx.x;
    const int warp = tid >> 5, lane = tid & 31;
    const int gid = lane >> 2, tig = lane & 3;
    const int wm = warp >> 1, wn = warp & 1;
    const int bm = blockIdx.y * 64, bn = blockIdx.x * 64;
    float acc[4][4] = {};

    for (int k0 = 0; k0 < K; k0 += 32) {
        // A: 64 rows x 32 f32 -> split to hi/lo smem
#pragma unroll
        for (int it = 0; it < 2; it++) {
            int j = tid * 2 + it;
            int row = j >> 3, c4 = j & 7;
            float4 v = *(const float4*)&A[(long)(bm + row) * K + k0 + c4 * 4];
            if (ADD2) {
                float4 w = *(const float4*)&A2[(long)(bm + row) * K + k0 + c4 * 4];
                v.x += w.x; v.y += w.y; v.z += w.z; v.w += w.w;
            }
            uint32_t h0, l0, h1, l1;
            split2(v.x, v.y, h0, l0);
            split2(v.z, v.w, h1, l1);
            uint32_t* ph = (uint32_t*)&Ahs[row * AST + c4 * 4];
            uint32_t* pl = (uint32_t*)&Als[row * AST + c4 * 4];
            ph[0] = h0; ph[1] = h1;
            pl[0] = l0; pl[1] = l1;
        }
        // B: 64 rows x 32 bf16 (hi & lo) from global
        {
            int row = tid >> 2, seg = tid & 3;
            int brow = bn + row;
            uint4 vh = make_uint4(0, 0, 0, 0), vl = make_uint4(0, 0, 0, 0);
            if (brow < N) {
                vh = *(const uint4*)&Bh[(long)brow * K + k0 + seg * 8];
                vl = *(const uint4*)&Bl[(long)brow * K + k0 + seg * 8];
            }
            *(uint4*)&Bhs[row * AST + seg * 8] = vh;
            *(uint4*)&Bls[row * AST + seg * 8] = vl;
        }
        __syncthreads();

#pragma unroll
        for (int ks = 0; ks < 2; ks++) {
            int kk = ks * 16 + tig * 2;
            int r = wm * 16;
            uint32_t ah0 = *(const uint32_t*)&Ahs[(r + gid    ) * AST + kk    ];
            uint32_t ah1 = *(const uint32_t*)&Ahs[(r + gid + 8) * AST + kk    ];
            uint32_t ah2 = *(const uint32_t*)&Ahs[(r + gid    ) * AST + kk + 8];
            uint32_t ah3 = *(const uint32_t*)&Ahs[(r + gid + 8) * AST + kk + 8];
            uint32_t al0 = *(const uint32_t*)&Als[(r + gid    ) * AST + kk    ];
            uint32_t al1 = *(const uint32_t*)&Als[(r + gid + 8) * AST + kk    ];
            uint32_t al2 = *(const uint32_t*)&Als[(r + gid    ) * AST + kk + 8];
            uint32_t al3 = *(const uint32_t*)&Als[(r + gid + 8) * AST + kk + 8];
#pragma unroll
            for (int nb = 0; nb < 4; nb++) {
                int nr = wn * 32 + nb * 8 + gid;
                uint32_t bh0 = *(const uint32_t*)&Bhs[nr * AST + kk    ];
                uint32_t bh1 = *(const uint32_t*)&Bhs[nr * AST + kk + 8];
                uint32_t bl0 = *(const uint32_t*)&Bls[nr * AST + kk    ];
                uint32_t bl1 = *(const uint32_t*)&Bls[nr * AST + kk + 8];
                mma_bf16(acc[nb], ah0, ah1, ah2, ah3, bh0, bh1);
                mma_bf16(acc[nb], ah0, ah1, ah2, ah3, bl0, bl1);
                mma_bf16(acc[nb], al0, al1, al2, al3, bh0, bh1);
            }
        }
        __syncthreads();
    }

    // epilogue
    const int rowA = bm + wm * 16 + gid, rowB = rowA + 8;
#pragma unroll
    for (int nb = 0; nb < 4; nb++) {
        int col = bn + wn * 32 + nb * 8 + tig * 2;
        if (col >= N) continue;
        float b0 = bias[col], b1 = bias[col + 1];
        float v0 = acc[nb][0] + b0, v1 = acc[nb][1] + b1;
        float v2 = acc[nb][2] + b0, v3 = acc[nb][3] + b1;
        if (RELU) {
            v0 = fmaxf(v0, 0.f); v1 = fmaxf(v1, 0.f);
            v2 = fmaxf(v2, 0.f); v3 = fmaxf(v3, 0.f);
        }
        if (QKV) {
            int sec = col >> 7, hh = (col & 127) >> 5, d = col & 31;
            if (sec == 0) {
                *(uint32_t*)&qb[((hh << 12) + rowA) * 32 + d] = pack_bf16(v0, v1);
                *(uint32_t*)&qb[((hh << 12) + rowB) * 32 + d] = pack_bf16(v2, v3);
            } else if (sec == 1) {
                *(uint32_t*)&kbuf[((hh << 12) + rowA) * 32 + d] = pack_bf16(v0, v1);
                *(uint32_t*)&kbuf[((hh << 12) + rowB) * 32 + d] = pack_bf16(v2, v3);
            } else {
                vtb[((hh * 32 + d    ) << 12) + rowA] = __float2bfloat16(v0);
                vtb[((hh * 32 + d + 1) << 12) + rowA] = __float2bfloat16(v1);
                vtb[((hh * 32 + d    ) << 12) + rowB] = __float2bfloat16(v2);
                vtb[((hh * 32 + d + 1) << 12) + rowB] = __float2bfloat16(v3);
            }
        } else {
            *(float2*)&C[(long)rowA * N + col] = make_float2(v0, v1);
            *(float2*)&C[(long)rowB * N + col] = make_float2(v2, v3);
        }
    }
}

// ---------------- BatchNorm: two-pass, coalesced ----------------
template <int NIN>
__global__ __launch_bounds__(256) void bn_reduce(const float* __restrict__ in1,
        const float* __restrict__ in2, const float* __restrict__ in3,
        float* __restrict__ sums) {
    __shared__ float shs[8][128];
    __shared__ float shq[8][128];
    int tx = threadIdx.x & 31, ty = threadIdx.x >> 5;
    float4 s = make_float4(0.f, 0.f, 0.f, 0.f);
    float4 q = make_float4(0.f, 0.f, 0.f, 0.f);
    for (int r = blockIdx.x * 8 + ty; r < NN; r += 64 * 8) {
        float4 v = ((const float4*)in1)[r * 32 + tx];
        if (NIN >= 2) {
            float4 w = ((const float4*)in2)[r * 32 + tx];
            v.x += w.x; v.y += w.y; v.z += w.z; v.w += w.w;
        }
        if (NIN >= 3) {
            float4 w = ((const float4*)in3)[r * 32 + tx];
            v.x += w.x; v.y += w.y; v.z += w.z; v.w += w.w;
        }
        s.x += v.x; s.y += v.y; s.z += v.z; s.w += v.w;
        q.x += v.x * v.x; q.y += v.y * v.y; q.z += v.z * v.z; q.w += v.w * v.w;
    }
    shs[ty][tx * 4 + 0] = s.x; shs[ty][tx * 4 + 1] = s.y;
    shs[ty][tx * 4 + 2] = s.z; shs[ty][tx * 4 + 3] = s.w;
    shq[ty][tx * 4 + 0] = q.x; shq[ty][tx * 4 + 1] = q.y;
    shq[ty][tx * 4 + 2] = q.z; shq[ty][tx * 4 + 3] = q.w;
    __syncthreads();
    int c = threadIdx.x;
    if (c < 128) {
        float ts = 0.f, tq = 0.f;
#pragma unroll
        for (int k = 0; k < 8; k++) { ts += shs[k][c]; tq += shq[k][c]; }
        atomicAdd(&sums[c], ts);
        atomicAdd(&sums[CC + c], tq);
    }
}

template <int NIN>
__global__ __launch_bounds__(256) void bn_apply(const float* __restrict__ in1,
        const float* __restrict__ in2, const float* __restrict__ in3,
        const float* __restrict__ g, const float* __restrict__ b,
        const float* __restrict__ sums, float* __restrict__ out) {
    int i = blockIdx.x * 256 + threadIdx.x;
    if (i >= NN * 32) return;
    int c4 = i & 31;
    float4 v = ((const float4*)in1)[i];
    if (NIN >= 2) {
        float4 w = ((const float4*)in2)[i];
        v.x += w.x; v.y += w.y; v.z += w.z; v.w += w.w;
    }
    if (NIN >= 3) {
        float4 w = ((const float4*)in3)[i];
        v.x += w.x; v.y += w.y; v.z += w.z; v.w += w.w;
    }
    float o[4] = {v.x, v.y, v.z, v.w};
#pragma unroll
    for (int k = 0; k < 4; k++) {
        int c = c4 * 4 + k;
        float mean = sums[c] * (1.f / NN);
        float var  = sums[CC + c] * (1.f / NN) - mean * mean;
        float sc   = rsqrtf(var + BN_EPS) * g[c];
        o[k] = (o[k] - mean) * sc + b[c];
    }
    ((float4*)out)[i] = make_float4(o[0], o[1], o[2], o[3]);
}

// ---------------- mma.sync flash attention ----------------
#define EXP2_SCALE 0.25503480f
#define QK_STRIDE 40
#define VT_STRIDE 136

__global__ __launch_bounds__(256, 1) void mma_attn(const __nv_bfloat16* __restrict__ qb,
        const __nv_bfloat16* __restrict__ kb, const __nv_bfloat16* __restrict__ vtb,
        float* __restrict__ out) {
    __shared__ uint16_t Qs[128 * QK_STRIDE];
    __shared__ uint16_t Ks[128 * QK_STRIDE];
    __shared__ uint16_t Vts[32 * VT_STRIDE];

    const int tid = threadIdx.x;
    const int wid = tid >> 5, lane = tid & 31;
    const int gid = lane >> 2, tig = lane & 3;
    const int h = blockIdx.y;
    const int qbase = blockIdx.x * 128;
    const int r0 = wid * 16;

    const uint16_t* Qg = (const uint16_t*)(qb + ((long)h * NN + qbase) * 32);
#pragma unroll
    for (int it = 0; it < 2; it++) {
        int i = tid + it * 256;
        int row = i >> 2, seg = i & 3;
        *(uint4*)&Qs[row * QK_STRIDE + seg * 8] = *(const uint4*)&Qg[row * 32 + seg * 8];
    }
    __syncthreads();

    uint32_t aq[2][4];
#pragma unroll
    for (int t = 0; t < 2; t++) {
        int k = t * 16 + tig * 2;
        aq[t][0] = *(const uint32_t*)&Qs[(r0 + gid    ) * QK_STRIDE + k    ];
        aq[t][1] = *(const uint32_t*)&Qs[(r0 + gid + 8) * QK_STRIDE + k    ];
        aq[t][2] = *(const uint32_t*)&Qs[(r0 + gid    ) * QK_STRIDE + k + 8];
        aq[t][3] = *(const uint32_t*)&Qs[(r0 + gid + 8) * QK_STRIDE + k + 8];
    }

    float oacc[4][4] = {};
    float rs0 = 0.f, rs1 = 0.f;

    for (int kt = 0; kt < NN / 128; kt++) {
        const int kb0 = kt * 128;
        __syncthreads();
        const uint16_t* Kg = (const uint16_t*)(kb + ((long)h * NN + kb0) * 32);
#pragma unroll
        for (int it = 0; it < 2; it++) {
            int i = tid + it * 256;
            int row = i >> 2, seg = i & 3;
            *(uint4*)&Ks[row * QK_STRIDE + seg * 8] = *(const uint4*)&Kg[row * 32 + seg * 8];
        }
        const uint16_t* Vg = (const uint16_t*)(vtb + ((long)h * 32) * NN + kb0);
#pragma unroll
        for (int it = 0; it < 2; it++) {
            int i = tid + it * 256;
            int d = i >> 4, seg = i & 15;
            *(uint4*)&Vts[d * VT_STRIDE + seg * 8] = *(const uint4*)&Vg[(long)d * NN + seg * 8];
        }
        __syncthreads();

        float sacc[16][4];
#pragma unroll
        for (int j = 0; j < 16; j++) { sacc[j][0] = sacc[j][1] = sacc[j][2] = sacc[j][3] = 0.f; }
#pragma unroll
        for (int j = 0; j < 16; j++) {
#pragma unroll
            for (int t = 0; t < 2; t++) {
                int k = t * 16 + tig * 2;
                uint32_t b0 = *(const uint32_t*)&Ks[(8 * j + gid) * QK_STRIDE + k    ];
                uint32_t b1 = *(const uint32_t*)&Ks[(8 * j + gid) * QK_STRIDE + k + 8];
                mma_bf16(sacc[j], aq[t][0], aq[t][1], aq[t][2], aq[t][3], b0, b1);
            }
        }

        uint32_t pf[16][2];
#pragma unroll
        for (int j = 0; j < 16; j++) {
            float p0 = fast_exp2(sacc[j][0] * EXP2_SCALE);
            float p1 = fast_exp2(sacc[j][1] * EXP2_SCALE);
            float p2 = fast_exp2(sacc[j][2] * EXP2_SCALE);
            float p3 = fast_exp2(sacc[j][3] * EXP2_SCALE);
            rs0 += p0 + p1;
            rs1 += p2 + p3;
            pf[j][0] = pack_bf16(p0, p1);
            pf[j][1] = pack_bf16(p2, p3);
        }

#pragma unroll
        for (int t = 0; t < 8; t++) {
            uint32_t a0 = pf[2 * t][0], a1 = pf[2 * t][1];
            uint32_t a2 = pf[2 * t + 1][0], a3 = pf[2 * t + 1][1];
            int k = t * 16 + tig * 2;
#pragma unroll
            for (int n = 0; n < 4; n++) {
                uint32_t b0 = *(const uint32_t*)&Vts[(8 * n + gid) * VT_STRIDE + k    ];
                uint32_t b1 = *(const uint32_t*)&Vts[(8 * n + gid) * VT_STRIDE + k + 8];
                mma_bf16(oacc[n], a0, a1, a2, a3, b0, b1);
            }
        }
    }

    rs0 += __shfl_xor_sync(0xFFFFFFFF, rs0, 1);
    rs0 += __shfl_xor_sync(0xFFFFFFFF, rs0, 2);
    rs1 += __shfl_xor_sync(0xFFFFFFFF, rs1, 1);
    rs1 += __shfl_xor_sync(0xFFFFFFFF, rs1, 2);
    float inv0 = 1.f / rs0, inv1 = 1.f / rs1;

    int rowA = qbase + r0 + gid, rowB = rowA + 8;
    float* poA = out + (long)rowA * CC + h * 32 + tig * 2;
    float* poB = out + (long)rowB * CC + h * 32 + tig * 2;
#pragma unroll
    for (int n = 0; n < 4; n++) {
        *(float2*)(poA + n * 8) = make_float2(oacc[n][0] * inv0, oacc[n][1] * inv0);
        *(float2*)(poB + n * 8) = make_float2(oacc[n][2] * inv1, oacc[n][3] * inv1);
    }
}

// ---------------- final head dot ----------------
__global__ void head_final(const float* __restrict__ t32, const float* __restrict__ w,
                           const float* __restrict__ b, float* __restrict__ out) {
    int n = blockIdx.x * blockDim.x + threadIdx.x;
    if (n >= NN) return;
    float s = b[0];
#pragma unroll
    for (int k = 0; k < 32; k++) s = fmaf(t32[n * 32 + k], w[k], s);
    out[n] = s;
}

// ---------------- host orchestration ----------------
static __nv_bfloat16 *s_whi, *s_wlo;

static void launch_tc(const float* A, const float* A2, int woff, const float* bias,
                      float* C, int M, int N, int K, bool relu, bool add2) {
    dim3 grid((N + 63) / 64, M / 64);
    const __nv_bfloat16* Bh = s_whi + woff;
    const __nv_bfloat16* Bl = s_wlo + woff;
    if (add2) {
        if (relu) gemm_tc<true, true, false><<<grid, 256>>>(A, A2, Bh, Bl, bias, C,
                                                            nullptr, nullptr, nullptr, M, N, K);
        else      gemm_tc<false, true, false><<<grid, 256>>>(A, A2, Bh, Bl, bias, C,
                                                             nullptr, nullptr, nullptr, M, N, K);
    } else {
        if (relu) gemm_tc<true, false, false><<<grid, 256>>>(A, nullptr, Bh, Bl, bias, C,
                                                             nullptr, nullptr, nullptr, M, N, K);
        else      gemm_tc<false, false, false><<<grid, 256>>>(A, nullptr, Bh, Bl, bias, C,
                                                              nullptr, nullptr, nullptr, M, N, K);
    }
}

static void launch_bn2(const float* in1, const float* in2, const float* g, const float* b,
                       float* sums, float* out) {
    cudaMemsetAsync(sums, 0, 2 * CC * sizeof(float));
    bn_reduce<2><<<64, 256>>>(in1, in2, nullptr, sums);
    bn_apply<2><<<NN * 32 / 256, 256>>>(in1, in2, nullptr, g, b, sums, out);
}
static void launch_bn3(const float* in1, const float* in2, const float* in3, const float* g,
                       const float* b, float* sums, float* out) {
    cudaMemsetAsync(sums, 0, 2 * CC * sizeof(float));
    bn_reduce<3><<<64, 256>>>(in1, in2, in3, sums);
    bn_apply<3><<<NN * 32 / 256, 256>>>(in1, in2, in3, g, b, sums, out);
}

extern "C" void kernel_launch(void* const* d_in, const int* in_sizes, int n_in,
                              void* d_out, int out_size) {
    const float* x_in      = (const float*)d_in[0];
    const int*   edge      = (const int*)  d_in[1];
    const float* gin_w1    = (const float*)d_in[2];
    const float* gin_b1    = (const float*)d_in[3];
    const float* gin_w2    = (const float*)d_in[4];
    const float* gin_b2    = (const float*)d_in[5];
    const float* attn_in_w = (const float*)d_in[6];
    const float* attn_in_b = (const float*)d_in[7];
    const float* attn_o_w  = (const float*)d_in[8];
    const float* attn_o_b  = (const float*)d_in[9];
    const float* n1_g = (const float*)d_in[10];
    const float* n1_b = (const float*)d_in[11];
    const float* n2_g = (const float*)d_in[12];
    const float* n2_b = (const float*)d_in[13];
    const float* n3_g = (const float*)d_in[14];
    const float* n3_b = (const float*)d_in[15];
    const float* mlp_w1 = (const float*)d_in[16];
    const float* mlp_b1 = (const float*)d_in[17];
    const float* mlp_w2 = (const float*)d_in[18];
    const float* mlp_b2 = (const float*)d_in[19];
    const float* hw1 = (const float*)d_in[20];
    const float* hb1 = (const float*)d_in[21];
    const float* hw2 = (const float*)d_in[22];
    const float* hb2 = (const float*)d_in[23];
    const float* hw3 = (const float*)d_in[24];
    const float* hb3 = (const float*)d_in[25];
    float* out = (float*)d_out;

    int E = in_sizes[1] / 2;

    float *p_x, *p_agg, *p_t1, *p_t2, *p_h1, *p_h2, *p_bnsum;
    int *p_deg;
    __nv_bfloat16 *p_qb, *p_kb, *p_vtb;
    cudaGetSymbolAddress((void**)&p_x,  g_x);
    cudaGetSymbolAddress((void**)&p_agg, g_agg);
    cudaGetSymbolAddress((void**)&p_t1, g_t1);
    cudaGetSymbolAddress((void**)&p_t2, g_t2);
    cudaGetSymbolAddress((void**)&p_h1, g_h1);
    cudaGetSymbolAddress((void**)&p_h2, g_h2);
    cudaGetSymbolAddress((void**)&p_bnsum, g_bnsum);
    cudaGetSymbolAddress((void**)&p_deg, g_deg);
    cudaGetSymbolAddress((void**)&p_qb, g_qb);
    cudaGetSymbolAddress((void**)&p_kb, g_kb);
    cudaGetSymbolAddress((void**)&p_vtb, g_vtb);
    cudaGetSymbolAddress((void**)&s_whi, g_whi);
    cudaGetSymbolAddress((void**)&s_wlo, g_wlo);

    const int NC4 = NN * CC / 4;

    // ---- weight hi/lo conversion (all layers at once) ----
    conv_w<<<(WTOTAL + 255) / 256, 256>>>(gin_w1, gin_w2, attn_in_w, attn_o_w,
                                          mlp_w1, mlp_w2, hw1, hw2, hw3);

    // ---- CSR build ----
    cudaMemsetAsync(p_deg, 0, (NN + 1) * sizeof(int));
    hist_kernel<<<(E + 255) / 256, 256>>>(edge, E);
    scan_kernel<<<1, 1024>>>();
    fill_kernel<<<(E + 255) / 256, 256>>>(edge, E);

    copy_kernel<<<(NC4 + 255) / 256, 256>>>(x_in, p_x, NC4);

    for (int i = 0; i < LL; i++) {
        const float* gb1 = gin_b1 + (long)i * CC;
        const float* gb2 = gin_b2 + (long)i * CC;
        const float* aib = attn_in_b + (long)i * 3 * CC;
        const float* aob = attn_o_b + (long)i * CC;
        const float* mb1 = mlp_b1 + (long)i * 2 * CC;
        const float* mb2 = mlp_b2 + (long)i * CC;

        // ---- GIN branch ----
        gather_kernel<<<NN / 8, 256>>>(p_x, p_agg);
        launch_tc(p_agg, nullptr, WOFF_GIN1 + i * CC * CC, gb1, p_t1, NN, CC, CC, true, false);
        launch_tc(p_t1, nullptr, WOFF_GIN2 + i * CC * CC, gb2, p_t2, NN, CC, CC, false, false);
        launch_bn2(p_t2, p_x, n1_g + i * CC, n1_b + i * CC, p_bnsum, p_h1);

        // ---- attention branch: fused qkv gemm -> bf16 q/k/v^T ----
        {
            dim3 grid(384 / 64, NN / 64);
            gemm_tc<false, false, true><<<grid, 256>>>(p_x, nullptr,
                s_whi + WOFF_AIN + i * 3 * CC * CC, s_wlo + WOFF_AIN + i * 3 * CC * CC,
                aib, nullptr, p_qb, p_kb, p_vtb, NN, 3 * CC, CC);
        }
        mma_attn<<<dim3(NN / 128, HEADS), 256>>>(p_qb, p_kb, p_vtb, p_agg);
        launch_tc(p_agg, nullptr, WOFF_AOUT + i * CC * CC, aob, p_t2, NN, CC, CC, false, false);
        launch_bn2(p_t2, p_x, n2_g + i * CC, n2_b + i * CC, p_bnsum, p_h2);

        // ---- MLP ----
        launch_tc(p_h1, p_h2, WOFF_MW1 + i * 2 * CC * CC, mb1, p_t1, NN, 2 * CC, CC, true, true);
        launch_tc(p_t1, nullptr, WOFF_MW2 + i * 2 * CC * CC, mb2, p_t2, NN, CC, 2 * CC, false, false);
        launch_bn3(p_h1, p_h2, p_t2, n3_g + i * CC, n3_b + i * CC, p_bnsum, p_x);
    }

    // ---- head MLP ----
    launch_tc(p_x, nullptr, WOFF_HW1, hb1, p_t1, NN, CC / 2, CC, true, false);
    launch_tc(p_t1, nullptr, WOFF_HW2, hb2, p_t2, NN, CC / 4, CC / 2, true, false);
    head_final<<<(NN + 255) / 256, 256>>>(p_t2, hw3, hb3, out);
}

// round 8
// speedup vs baseline: 7.4321x; 1.0799x over previous
#include <cuda_runtime.h>
#include <cuda_bf16.h>
#include <cstdint>

#define NN 4096
#define CC 128
#define LL 4
#define HEADS 4
#define BN_EPS 1e-5f
#define EMAX 262144

// ---------------- scratch (static device globals; no allocation) ----------------
__device__ float g_x  [NN * CC];
__device__ float g_agg[NN * CC];
__device__ float g_t1 [NN * 384];
__device__ float g_t2 [NN * CC];     // h in MLP stage
__device__ float g_h1 [NN * CC];     // w1' = t2_gin + x
__device__ float g_h2 [NN * CC];     // w2' = t2_attn + x
__device__ float g_bnsums[12 * 2 * CC];
__device__ int   g_deg[NN + 1];
__device__ int   g_cur[NN];
__device__ int   g_csr[EMAX];
__device__ __nv_bfloat16 g_qb [HEADS * NN * 32];
__device__ __nv_bfloat16 g_kb [HEADS * NN * 32];
__device__ __nv_bfloat16 g_vtb[HEADS * 32 * NN];

// concatenated hi/lo bf16 weights
#define WOFF_GIN1 0
#define WOFF_GIN2 65536
#define WOFF_AIN  131072
#define WOFF_AOUT 327680
#define WOFF_MW1  393216
#define WOFF_MW2  524288
#define WTOTAL    655360
__device__ __nv_bfloat16 g_whi[WTOTAL];
__device__ __nv_bfloat16 g_wlo[WTOTAL];

// ---------------- mma.sync helpers ----------------
__device__ __forceinline__ void mma_bf16(float* d, uint32_t a0, uint32_t a1, uint32_t a2,
                                         uint32_t a3, uint32_t b0, uint32_t b1) {
    asm volatile(
        "mma.sync.aligned.m16n8k16.row.col.f32.bf16.bf16.f32 "
        "{%0,%1,%2,%3}, {%4,%5,%6,%7}, {%8,%9}, {%0,%1,%2,%3};"
        : "+f"(d[0]), "+f"(d[1]), "+f"(d[2]), "+f"(d[3])
        : "r"(a0), "r"(a1), "r"(a2), "r"(a3), "r"(b0), "r"(b1));
}
__device__ __forceinline__ float fast_exp2(float x) {
    float y; asm("ex2.approx.ftz.f32 %0, %1;" : "=f"(y) : "f"(x)); return y;
}
__device__ __forceinline__ uint32_t pack_bf16(float lo, float hi) {
    uint32_t r; asm("cvt.rn.bf16x2.f32 %0, %1, %2;" : "=r"(r) : "f"(hi), "f"(lo)); return r;
}
__device__ __forceinline__ void split2(float x, float y, uint32_t& hi, uint32_t& lo) {
    __nv_bfloat16 hx = __float2bfloat16(x), hy = __float2bfloat16(y);
    float lx = x - __bfloat162float(hx), ly = y - __bfloat162float(hy);
    hi = pack_bf16(__bfloat162float(hx), __bfloat162float(hy));
    lo = pack_bf16(lx, ly);
}

// ---------------- misc ----------------
__global__ void copy_kernel(const float* __restrict__ a, float* __restrict__ o, int n4) {
    int i = blockIdx.x * blockDim.x + threadIdx.x;
    if (i < n4) ((float4*)o)[i] = ((const float4*)a)[i];
}

// ---------------- weight hi/lo conversion ----------------
__global__ void conv_w(const float* __restrict__ w_gin1, const float* __restrict__ w_gin2,
                       const float* __restrict__ w_ain,  const float* __restrict__ w_aout,
                       const float* __restrict__ w_m1,   const float* __restrict__ w_m2) {
    int id = blockIdx.x * 256 + threadIdx.x;
    if (id >= WTOTAL) return;
    const float* src; int off;
    if      (id < WOFF_GIN2) { src = w_gin1; off = id; }
    else if (id < WOFF_AIN)  { src = w_gin2; off = id - WOFF_GIN2; }
    else if (id < WOFF_AOUT) { src = w_ain;  off = id - WOFF_AIN; }
    else if (id < WOFF_MW1)  { src = w_aout; off = id - WOFF_AOUT; }
    else if (id < WOFF_MW2)  { src = w_m1;   off = id - WOFF_MW1; }
    else                     { src = w_m2;   off = id - WOFF_MW2; }
    float v = src[off];
    __nv_bfloat16 h = __float2bfloat16(v);
    g_whi[id] = h;
    g_wlo[id] = __float2bfloat16(v - __bfloat162float(h));
}

// ---------------- CSR build ----------------
__global__ void hist_kernel(const int* __restrict__ ei, int E) {
    int e = blockIdx.x * blockDim.x + threadIdx.x;
    if (e < E) atomicAdd(&g_deg[ei[E + e] + 1], 1);
}

__global__ void scan_kernel() {
    __shared__ int part[1024];
    int t = threadIdx.x;
    int base = t * 4;
    int x0 = g_deg[base], x1 = g_deg[base + 1], x2 = g_deg[base + 2], x3 = g_deg[base + 3];
    x1 += x0; x2 += x1; x3 += x2;
    part[t] = x3;
    __syncthreads();
    for (int off = 1; off < 1024; off <<= 1) {
        int v = (t >= off) ? part[t - off] : 0;
        __syncthreads();
        part[t] += v;
        __syncthreads();
    }
    int add = (t > 0) ? part[t - 1] : 0;
    int v0 = x0 + add, v1 = x1 + add, v2 = x2 + add, v3 = x3 + add;
    g_deg[base] = v0; g_deg[base + 1] = v1; g_deg[base + 2] = v2; g_deg[base + 3] = v3;
    g_cur[base] = v0; g_cur[base + 1] = v1; g_cur[base + 2] = v2; g_cur[base + 3] = v3;
    __syncthreads();
    if (t == 0) g_deg[NN] += g_deg[NN - 1];
}

__global__ void fill_kernel(const int* __restrict__ ei, int E) {
    int e = blockIdx.x * blockDim.x + threadIdx.x;
    if (e >= E) return;
    int s = ei[e], d = ei[E + e];
    int pos = atomicAdd(&g_cur[d], 1);
    g_csr[pos] = s;
}

// ---------------- GIN gather ----------------
__global__ __launch_bounds__(256) void gather_kernel(const float* __restrict__ x,
                                                     float* __restrict__ agg) {
    int wg = (blockIdx.x * 256 + threadIdx.x) >> 5;
    int lane = threadIdx.x & 31;
    if (wg >= NN) return;
    int beg = g_deg[wg], end = g_deg[wg + 1];
    float4 acc = *(const float4*)&x[(long)wg * CC + lane * 4];
    for (int j = beg; j < end; j++) {
        int s = g_csr[j];
        float4 v = *(const float4*)&x[(long)s * CC + lane * 4];
        acc.x += v.x; acc.y += v.y; acc.z += v.z; acc.w += v.w;
    }
    *(float4*)&agg[(long)wg * CC + lane * 4] = acc;
}

// ---------------- tensor-core GEMM (hi/lo split) ----------------
// LMODE 0: A fp32 plain. LMODE 2: A = aff1(A) + aff2(A2), coeffs from s1/s2; writes hout (bx==0).
// EMODE 0: store. 1: relu store. 2: qkv scatter. 3: w=v+xres, store w, reduce col sums into sums_out.
#define AST 40
template <int LMODE, int EMODE>
__global__ __launch_bounds__(256) void gemm_tc(const float* __restrict__ A,
        const float* __restrict__ A2,
        const __nv_bfloat16* __restrict__ Bh, const __nv_bfloat16* __restrict__ Bl,
        const float* __restrict__ bias, float* __restrict__ C,
        __nv_bfloat16* __restrict__ qb, __nv_bfloat16* __restrict__ kbuf,
        __nv_bfloat16* __restrict__ vtb,
        const float* __restrict__ xres, float* __restrict__ sums_out,
        const float* __restrict__ s1, const float* __restrict__ g1, const float* __restrict__ b1,
        const float* __restrict__ s2, const float* __restrict__ g2, const float* __restrict__ b2,
        float* __restrict__ hout, int M, int N, int K) {
    __shared__ uint16_t Ahs[64 * AST], Als[64 * AST];
    __shared__ uint16_t Bhs[64 * AST], Bls[64 * AST];
    __shared__ float csc1[128], cof1[128], csc2[128], cof2[128];
    const int tid = threadIdx.x;
    const int warp = tid >> 5, lane = tid & 31;
    const int gid = lane >> 2, tig = lane & 3;
    const int wm = warp >> 1, wn = warp & 1;
    const int bm = blockIdx.y * 64, bn = blockIdx.x * 64;
    float acc[4][4] = {};

    if (LMODE == 2) {
        int c = tid & 127;
        const float* ss = (tid < 128) ? s1 : s2;
        const float* gg = (tid < 128) ? g1 : g2;
        const float* bb2 = (tid < 128) ? b1 : b2;
        float mean = ss[c] * (1.f / NN);
        float var  = ss[CC + c] * (1.f / NN) - mean * mean;
        float sc   = rsqrtf(var + BN_EPS) * gg[c];
        float off  = bb2[c] - mean * sc;
        if (tid < 128) { csc1[c] = sc; cof1[c] = off; }
        else           { csc2[c] = sc; cof2[c] = off; }
        __syncthreads();
    }

    for (int k0 = 0; k0 < K; k0 += 32) {
#pragma unroll
        for (int it = 0; it < 2; it++) {
            int j = tid * 2 + it;
            int row = j >> 3, c4 = j & 7;
            int cbase = k0 + c4 * 4;
            float4 v = *(const float4*)&A[(long)(bm + row) * K + cbase];
            if (LMODE == 2) {
                float4 w = *(const float4*)&A2[(long)(bm + row) * K + cbase];
                v.x = v.x * csc1[cbase]     + cof1[cbase]     + w.x * csc2[cbase]     + cof2[cbase];
                v.y = v.y * csc1[cbase + 1] + cof1[cbase + 1] + w.y * csc2[cbase + 1] + cof2[cbase + 1];
                v.z = v.z * csc1[cbase + 2] + cof1[cbase + 2] + w.z * csc2[cbase + 2] + cof2[cbase + 2];
                v.w = v.w * csc1[cbase + 3] + cof1[cbase + 3] + w.w * csc2[cbase + 3] + cof2[cbase + 3];
                if (blockIdx.x == 0)
                    *(float4*)&hout[(long)(bm + row) * K + cbase] = v;
            }
            uint32_t h0, l0, h1, l1;
            split2(v.x, v.y, h0, l0);
            split2(v.z, v.w, h1, l1);
            uint32_t* ph = (uint32_t*)&Ahs[row * AST + c4 * 4];
            uint32_t* pl = (uint32_t*)&Als[row * AST + c4 * 4];
            ph[0] = h0; ph[1] = h1;
            pl[0] = l0; pl[1] = l1;
        }
        {
            int row = tid >> 2, seg = tid & 3;
            int brow = bn + row;
            uint4 vh = make_uint4(0, 0, 0, 0), vl = make_uint4(0, 0, 0, 0);
            if (brow < N) {
                vh = *(const uint4*)&Bh[(long)brow * K + k0 + seg * 8];
                vl = *(const uint4*)&Bl[(long)brow * K + k0 + seg * 8];
            }
            *(uint4*)&Bhs[row * AST + seg * 8] = vh;
            *(uint4*)&Bls[row * AST + seg * 8] = vl;
        }
        __syncthreads();

#pragma unroll
        for (int ks = 0; ks < 2; ks++) {
            int kk = ks * 16 + tig * 2;
            int r = wm * 16;
            uint32_t ah0 = *(const uint32_t*)&Ahs[(r + gid    ) * AST + kk    ];
            uint32_t ah1 = *(const uint32_t*)&Ahs[(r + gid + 8) * AST + kk    ];
            uint32_t ah2 = *(const uint32_t*)&Ahs[(r + gid    ) * AST + kk + 8];
            uint32_t ah3 = *(const uint32_t*)&Ahs[(r + gid + 8) * AST + kk + 8];
            uint32_t al0 = *(const uint32_t*)&Als[(r + gid    ) * AST + kk    ];
            uint32_t al1 = *(const uint32_t*)&Als[(r + gid + 8) * AST + kk    ];
            uint32_t al2 = *(const uint32_t*)&Als[(r + gid    ) * AST + kk + 8];
            uint32_t al3 = *(const uint32_t*)&Als[(r + gid + 8) * AST + kk + 8];
#pragma unroll
            for (int nb = 0; nb < 4; nb++) {
                int nr = wn * 32 + nb * 8 + gid;
                uint32_t bh0 = *(const uint32_t*)&Bhs[nr * AST + kk    ];
                uint32_t bh1 = *(const uint32_t*)&Bhs[nr * AST + kk + 8];
                uint32_t bl0 = *(const uint32_t*)&Bls[nr * AST + kk    ];
                uint32_t bl1 = *(const uint32_t*)&Bls[nr * AST + kk + 8];
                mma_bf16(acc[nb], ah0, ah1, ah2, ah3, bh0, bh1);
                mma_bf16(acc[nb], ah0, ah1, ah2, ah3, bl0, bl1);
                mma_bf16(acc[nb], al0, al1, al2, al3, bh0, bh1);
            }
        }
        __syncthreads();
    }

    const int rowA = bm + wm * 16 + gid, rowB = rowA + 8;
#pragma unroll
    for (int nb = 0; nb < 4; nb++) {
        int col = bn + wn * 32 + nb * 8 + tig * 2;
        if (col >= N) continue;
        float b0 = bias[col], b1v = bias[col + 1];
        float v0 = acc[nb][0] + b0, v1 = acc[nb][1] + b1v;
        float v2 = acc[nb][2] + b0, v3 = acc[nb][3] + b1v;
        if (EMODE == 1) {
            v0 = fmaxf(v0, 0.f); v1 = fmaxf(v1, 0.f);
            v2 = fmaxf(v2, 0.f); v3 = fmaxf(v3, 0.f);
        }
        if (EMODE == 2) {
            int sec = col >> 7, hh = (col & 127) >> 5, d = col & 31;
            if (sec == 0) {
                *(uint32_t*)&qb[((hh << 12) + rowA) * 32 + d] = pack_bf16(v0, v1);
                *(uint32_t*)&qb[((hh << 12) + rowB) * 32 + d] = pack_bf16(v2, v3);
            } else if (sec == 1) {
                *(uint32_t*)&kbuf[((hh << 12) + rowA) * 32 + d] = pack_bf16(v0, v1);
                *(uint32_t*)&kbuf[((hh << 12) + rowB) * 32 + d] = pack_bf16(v2, v3);
            } else {
                vtb[((hh * 32 + d    ) << 12) + rowA] = __float2bfloat16(v0);
                vtb[((hh * 32 + d + 1) << 12) + rowA] = __float2bfloat16(v1);
                vtb[((hh * 32 + d    ) << 12) + rowB] = __float2bfloat16(v2);
                vtb[((hh * 32 + d + 1) << 12) + rowB] = __float2bfloat16(v3);
            }
        } else if (EMODE == 3) {
            float2 xA = *(const float2*)&xres[(long)rowA * N + col];
            float2 xB = *(const float2*)&xres[(long)rowB * N + col];
            float w0 = v0 + xA.x, w1 = v1 + xA.y;
            float w2 = v2 + xB.x, w3 = v3 + xB.y;
            *(float2*)&C[(long)rowA * N + col] = make_float2(w0, w1);
            *(float2*)&C[(long)rowB * N + col] = make_float2(w2, w3);
            float cs0 = w0 + w2, cs1 = w1 + w3;
            float cq0 = w0 * w0 + w2 * w2, cq1 = w1 * w1 + w3 * w3;
#pragma unroll
            for (int mk = 4; mk < 32; mk <<= 1) {
                cs0 += __shfl_xor_sync(0xFFFFFFFF, cs0, mk);
                cs1 += __shfl_xor_sync(0xFFFFFFFF, cs1, mk);
                cq0 += __shfl_xor_sync(0xFFFFFFFF, cq0, mk);
                cq1 += __shfl_xor_sync(0xFFFFFFFF, cq1, mk);
            }
            if (gid == 0) {
                atomicAdd(&sums_out[col], cs0);
                atomicAdd(&sums_out[CC + col], cq0);
                atomicAdd(&sums_out[col + 1], cs1);
                atomicAdd(&sums_out[CC + col + 1], cq1);
            }
        } else {
            *(float2*)&C[(long)rowA * N + col] = make_float2(v0, v1);
            *(float2*)&C[(long)rowB * N + col] = make_float2(v2, v3);
        }
    }
}

// ---------------- BN affine apply: x = aff(u) ----------------
__global__ __launch_bounds__(256) void bn_affine(const float* __restrict__ u,
        const float* __restrict__ sums, const float* __restrict__ g,
        const float* __restrict__ b, float* __restrict__ out) {
    int i = blockIdx.x * 256 + threadIdx.x;
    if (i >= NN * 32) return;
    int c4 = i & 31;
    float4 v = ((const float4*)u)[i];
    float o[4] = {v.x, v.y, v.z, v.w};
#pragma unroll
    for (int k = 0; k < 4; k++) {
        int c = c4 * 4 + k;
        float mean = sums[c] * (1.f / NN);
        float var  = sums[CC + c] * (1.f / NN) - mean * mean;
        float sc   = rsqrtf(var + BN_EPS) * g[c];
        o[k] = (o[k] - mean) * sc + b[c];
    }
    ((float4*)out)[i] = make_float4(o[0], o[1], o[2], o[3]);
}

// ---------------- mma.sync flash attention ----------------
#define EXP2_SCALE 0.25503480f
#define QK_STRIDE 40
#define VT_STRIDE 136

__global__ __launch_bounds__(256, 1) void mma_attn(const __nv_bfloat16* __restrict__ qb,
        const __nv_bfloat16* __restrict__ kb, const __nv_bfloat16* __restrict__ vtb,
        float* __restrict__ out) {
    __shared__ uint16_t Qs[128 * QK_STRIDE];
    __shared__ uint16_t Ks[128 * QK_STRIDE];
    __shared__ uint16_t Vts[32 * VT_STRIDE];

    const int tid = threadIdx.x;
    const int wid = tid >> 5, lane = tid & 31;
    const int gid = lane >> 2, tig = lane & 3;
    const int h = blockIdx.y;
    const int qbase = blockIdx.x * 128;
    const int r0 = wid * 16;

    const uint16_t* Qg = (const uint16_t*)(qb + ((long)h * NN + qbase) * 32);
#pragma unroll
    for (int it = 0; it < 2; it++) {
        int i = tid + it * 256;
        int row = i >> 2, seg = i & 3;
        *(uint4*)&Qs[row * QK_STRIDE + seg * 8] = *(const uint4*)&Qg[row * 32 + seg * 8];
    }
    __syncthreads();

    uint32_t aq[2][4];
#pragma unroll
    for (int t = 0; t < 2; t++) {
        int k = t * 16 + tig * 2;
        aq[t][0] = *(const uint32_t*)&Qs[(r0 + gid    ) * QK_STRIDE + k    ];
        aq[t][1] = *(const uint32_t*)&Qs[(r0 + gid + 8) * QK_STRIDE + k    ];
        aq[t][2] = *(const uint32_t*)&Qs[(r0 + gid    ) * QK_STRIDE + k + 8];
        aq[t][3] = *(const uint32_t*)&Qs[(r0 + gid + 8) * QK_STRIDE + k + 8];
    }

    float oacc[4][4] = {};
    float rs0 = 0.f, rs1 = 0.f;

    for (int kt = 0; kt < NN / 128; kt++) {
        const int kb0 = kt * 128;
        __syncthreads();
        const uint16_t* Kg = (const uint16_t*)(kb + ((long)h * NN + kb0) * 32);
#pragma unroll
        for (int it = 0; it < 2; it++) {
            int i = tid + it * 256;
            int row = i >> 2, seg = i & 3;
            *(uint4*)&Ks[row * QK_STRIDE + seg * 8] = *(const uint4*)&Kg[row * 32 + seg * 8];
        }
        const uint16_t* Vg = (const uint16_t*)(vtb + ((long)h * 32) * NN + kb0);
#pragma unroll
        for (int it = 0; it < 2; it++) {
            int i = tid + it * 256;
            int d = i >> 4, seg = i & 15;
            *(uint4*)&Vts[d * VT_STRIDE + seg * 8] = *(const uint4*)&Vg[(long)d * NN + seg * 8];
        }
        __syncthreads();

        float sacc[16][4];
#pragma unroll
        for (int j = 0; j < 16; j++) { sacc[j][0] = sacc[j][1] = sacc[j][2] = sacc[j][3] = 0.f; }
#pragma unroll
        for (int j = 0; j < 16; j++) {
#pragma unroll
            for (int t = 0; t < 2; t++) {
                int k = t * 16 + tig * 2;
                uint32_t b0 = *(const uint32_t*)&Ks[(8 * j + gid) * QK_STRIDE + k    ];
                uint32_t b1 = *(const uint32_t*)&Ks[(8 * j + gid) * QK_STRIDE + k + 8];
                mma_bf16(sacc[j], aq[t][0], aq[t][1], aq[t][2], aq[t][3], b0, b1);
            }
        }

        uint32_t pf[16][2];
#pragma unroll
        for (int j = 0; j < 16; j++) {
            float p0 = fast_exp2(sacc[j][0] * EXP2_SCALE);
            float p1 = fast_exp2(sacc[j][1] * EXP2_SCALE);
            float p2 = fast_exp2(sacc[j][2] * EXP2_SCALE);
            float p3 = fast_exp2(sacc[j][3] * EXP2_SCALE);
            rs0 += p0 + p1;
            rs1 += p2 + p3;
            pf[j][0] = pack_bf16(p0, p1);
            pf[j][1] = pack_bf16(p2, p3);
        }

#pragma unroll
        for (int t = 0; t < 8; t++) {
            uint32_t a0 = pf[2 * t][0], a1 = pf[2 * t][1];
            uint32_t a2 = pf[2 * t + 1][0], a3 = pf[2 * t + 1][1];
            int k = t * 16 + tig * 2;
#pragma unroll
            for (int n = 0; n < 4; n++) {
                uint32_t b0 = *(const uint32_t*)&Vts[(8 * n + gid) * VT_STRIDE + k    ];
                uint32_t b1 = *(const uint32_t*)&Vts[(8 * n + gid) * VT_STRIDE + k + 8];
                mma_bf16(oacc[n], a0, a1, a2, a3, b0, b1);
            }
        }
    }

    rs0 += __shfl_xor_sync(0xFFFFFFFF, rs0, 1);
    rs0 += __shfl_xor_sync(0xFFFFFFFF, rs0, 2);
    rs1 += __shfl_xor_sync(0xFFFFFFFF, rs1, 1);
    rs1 += __shfl_xor_sync(0xFFFFFFFF, rs1, 2);
    float inv0 = 1.f / rs0, inv1 = 1.f / rs1;

    int rowA = qbase + r0 + gid, rowB = rowA + 8;
    float* poA = out + (long)rowA * CC + h * 32 + tig * 2;
    float* poB = out + (long)rowB * CC + h * 32 + tig * 2;
#pragma unroll
    for (int n = 0; n < 4; n++) {
        *(float2*)(poA + n * 8) = make_float2(oacc[n][0] * inv0, oacc[n][1] * inv0);
        *(float2*)(poB + n * 8) = make_float2(oacc[n][2] * inv1, oacc[n][3] * inv1);
    }
}

// ---------------- head MLP: warp-per-node, low smem ----------------
__global__ __launch_bounds__(256) void head_warp(const float* __restrict__ x,
        const float* __restrict__ w1, const float* __restrict__ b1,
        const float* __restrict__ w2, const float* __restrict__ b2,
        const float* __restrict__ w3, const float* __restrict__ b3,
        float* __restrict__ out) {
    __shared__ float y1s[8][64];
    __shared__ float y2s[8][32];
    int tid = threadIdx.x;
    int wid = tid >> 5, lane = tid & 31;
    int n = blockIdx.x * 8 + wid;

    // lane holds x[n, lane*4 .. lane*4+3]
    float4 xv = *(const float4*)&x[(long)n * 128 + lane * 4];

    // layer 1: 64 outputs, warp-reduced dot128
    for (int o = 0; o < 64; o++) {
        float4 wv = *(const float4*)&w1[o * 128 + lane * 4];
        float p = xv.x * wv.x + xv.y * wv.y + xv.z * wv.z + xv.w * wv.w;
#pragma unroll
        for (int mk = 16; mk > 0; mk >>= 1) p += __shfl_xor_sync(0xFFFFFFFF, p, mk);
        if (lane == 0) y1s[wid][o] = fmaxf(p + b1[o], 0.f);
    }
    __syncwarp();
    // layer 2: 32 outputs, dot64 (lane holds y1[2*lane], y1[2*lane+1])
    float ya = y1s[wid][lane * 2], yb = y1s[wid][lane * 2 + 1];
    for (int o = 0; o < 32; o++) {
        float2 wv = *(const float2*)&w2[o * 64 + lane * 2];
        float p = ya * wv.x + yb * wv.y;
#pragma unroll
        for (int mk = 16; mk > 0; mk >>= 1) p += __shfl_xor_sync(0xFFFFFFFF, p, mk);
        if (lane == 0) y2s[wid][o] = fmaxf(p + b2[o], 0.f);
    }
    __syncwarp();
    // layer 3: dot32
    float p = y2s[wid][lane] * w3[lane];
#pragma unroll
    for (int mk = 16; mk > 0; mk >>= 1) p += __shfl_xor_sync(0xFFFFFFFF, p, mk);
    if (lane == 0) out[n] = p + b3[0];
}

// ---------------- host orchestration ----------------
static __nv_bfloat16 *s_whi, *s_wlo;

extern "C" void kernel_launch(void* const* d_in, const int* in_sizes, int n_in,
                              void* d_out, int out_size) {
    const float* x_in      = (const float*)d_in[0];
    const int*   edge      = (const int*)  d_in[1];
    const float* gin_w1    = (const float*)d_in[2];
    const float* gin_b1    = (const float*)d_in[3];
    const float* gin_w2    = (const float*)d_in[4];
    const float* gin_b2    = (const float*)d_in[5];
    const float* attn_in_w = (const float*)d_in[6];
    const float* attn_in_b = (const float*)d_in[7];
    const float* attn_o_w  = (const float*)d_in[8];
    const float* attn_o_b  = (const float*)d_in[9];
    const float* n1_g = (const float*)d_in[10];
    const float* n1_b = (const float*)d_in[11];
    const float* n2_g = (const float*)d_in[12];
    const float* n2_b = (const float*)d_in[13];
    const float* n3_g = (const float*)d_in[14];
    const float* n3_b = (const float*)d_in[15];
    const float* mlp_w1 = (const float*)d_in[16];
    const float* mlp_b1 = (const float*)d_in[17];
    const float* mlp_w2 = (const float*)d_in[18];
    const float* mlp_b2 = (const float*)d_in[19];
    const float* hw1 = (const float*)d_in[20];
    const float* hb1 = (const float*)d_in[21];
    const float* hw2 = (const float*)d_in[22];
    const float* hb2 = (const float*)d_in[23];
    const float* hw3 = (const float*)d_in[24];
    const float* hb3 = (const float*)d_in[25];
    float* out = (float*)d_out;

    int E = in_sizes[1] / 2;

    float *p_x, *p_agg, *p_t1, *p_t2, *p_h1, *p_h2, *p_sums;
    int *p_deg;
    __nv_bfloat16 *p_qb, *p_kb, *p_vtb;
    cudaGetSymbolAddress((void**)&p_x,  g_x);
    cudaGetSymbolAddress((void**)&p_agg, g_agg);
    cudaGetSymbolAddress((void**)&p_t1, g_t1);
    cudaGetSymbolAddress((void**)&p_t2, g_t2);
    cudaGetSymbolAddress((void**)&p_h1, g_h1);
    cudaGetSymbolAddress((void**)&p_h2, g_h2);
    cudaGetSymbolAddress((void**)&p_sums, g_bnsums);
    cudaGetSymbolAddress((void**)&p_deg, g_deg);
    cudaGetSymbolAddress((void**)&p_qb, g_qb);
    cudaGetSymbolAddress((void**)&p_kb, g_kb);
    cudaGetSymbolAddress((void**)&p_vtb, g_vtb);
    cudaGetSymbolAddress((void**)&s_whi, g_whi);
    cudaGetSymbolAddress((void**)&s_wlo, g_wlo);

    const int NC4 = NN * CC / 4;

    conv_w<<<(WTOTAL + 255) / 256, 256>>>(gin_w1, gin_w2, attn_in_w, attn_o_w, mlp_w1, mlp_w2);
    cudaMemsetAsync(p_sums, 0, 12 * 2 * CC * sizeof(float));
    cudaMemsetAsync(p_deg, 0, (NN + 1) * sizeof(int));
    hist_kernel<<<(E + 255) / 256, 256>>>(edge, E);
    scan_kernel<<<1, 1024>>>();
    fill_kernel<<<(E + 255) / 256, 256>>>(edge, E);
    copy_kernel<<<(NC4 + 255) / 256, 256>>>(x_in, p_x, NC4);

    for (int i = 0; i < LL; i++) {
        const float* gb1 = gin_b1 + (long)i * CC;
        const float* gb2 = gin_b2 + (long)i * CC;
        const float* aib = attn_in_b + (long)i * 3 * CC;
        const float* aob = attn_o_b + (long)i * CC;
        const float* mb1 = mlp_b1 + (long)i * 2 * CC;
        const float* mb2 = mlp_b2 + (long)i * CC;
        float* s1 = p_sums + (3 * i + 0) * 2 * CC;
        float* s2 = p_sums + (3 * i + 1) * 2 * CC;
        float* s3 = p_sums + (3 * i + 2) * 2 * CC;

        // ---- GIN branch ----
        gather_kernel<<<NN / 8, 256>>>(p_x, p_agg);
        gemm_tc<0, 1><<<dim3(2, 64), 256>>>(p_agg, nullptr,
            s_whi + WOFF_GIN1 + i * CC * CC, s_wlo + WOFF_GIN1 + i * CC * CC, gb1, p_t1,
            nullptr, nullptr, nullptr, nullptr, nullptr,
            nullptr, nullptr, nullptr, nullptr, nullptr, nullptr, nullptr, NN, CC, CC);
        gemm_tc<0, 3><<<dim3(2, 64), 256>>>(p_t1, nullptr,
            s_whi + WOFF_GIN2 + i * CC * CC, s_wlo + WOFF_GIN2 + i * CC * CC, gb2, p_h1,
            nullptr, nullptr, nullptr, p_x, s1,
            nullptr, nullptr, nullptr, nullptr, nullptr, nullptr, nullptr, NN, CC, CC);

        // ---- attention branch ----
        gemm_tc<0, 2><<<dim3(6, 64), 256>>>(p_x, nullptr,
            s_whi + WOFF_AIN + i * 3 * CC * CC, s_wlo + WOFF_AIN + i * 3 * CC * CC, aib, nullptr,
            p_qb, p_kb, p_vtb, nullptr, nullptr,
            nullptr, nullptr, nullptr, nullptr, nullptr, nullptr, nullptr, NN, 3 * CC, CC);
        mma_attn<<<dim3(NN / 128, HEADS), 256>>>(p_qb, p_kb, p_vtb, p_agg);
        gemm_tc<0, 3><<<dim3(2, 64), 256>>>(p_agg, nullptr,
            s_whi + WOFF_AOUT + i * CC * CC, s_wlo + WOFF_AOUT + i * CC * CC, aob, p_h2,
            nullptr, nullptr, nullptr, p_x, s2,
            nullptr, nullptr, nullptr, nullptr, nullptr, nullptr, nullptr, NN, CC, CC);

        // ---- MLP: A = aff1(h1') + aff2(h2') (= h), write h, relu gemm ----
        gemm_tc<2, 1><<<dim3(4, 64), 256>>>(p_h1, p_h2,
            s_whi + WOFF_MW1 + i * 2 * CC * CC, s_wlo + WOFF_MW1 + i * 2 * CC * CC, mb1, p_t1,
            nullptr, nullptr, nullptr, nullptr, nullptr,
            s1, n1_g + i * CC, n1_b + i * CC, s2, n2_g + i * CC, n2_b + i * CC,
            p_t2, NN, 2 * CC, CC);
        gemm_tc<0, 3><<<dim3(2, 64), 256>>>(p_t1, nullptr,
            s_whi + WOFF_MW2 + i * 2 * CC * CC, s_wlo + WOFF_MW2 + i * 2 * CC * CC, mb2, p_agg,
            nullptr, nullptr, nullptr, p_t2, s3,
            nullptr, nullptr, nullptr, nullptr, nullptr, nullptr, nullptr, NN, CC, 2 * CC);
        bn_affine<<<NN * 32 / 256, 256>>>(p_agg, s3, n3_g + i * CC, n3_b + i * CC, p_x);
    }

    // ---- head ----
    head_warp<<<NN / 8, 256>>>(p_x, hw1, hb1, hw2, hb2, hw3, hb3, out);
}